// round 6
// baseline (speedup 1.0000x reference)
#include <cuda_runtime.h>
#include <math.h>

#define Bb   4
#define Ss   2048
#define Ee   512
#define Hh   8
#define HDd  64
#define BS   (Bb*Ss)            /* 8192 */
#define LDW  (2*Ee*Hh)          /* 8192 */
#define SCALE 0.044194173824159216f  /* 1/sqrt(512) */

/* ---- scratch (static device globals; no runtime allocation) ---- */
__device__ float g_M   [(size_t)Hh*Ee*Ee];   /* scale * Wq_h @ Wk_h^T, [h][c][c'] (8 MB)   */
__device__ float g_r   [Hh*Ee];              /* scale * Wk_h @ bq_h                        */
__device__ float g_beta[(size_t)Hh*BS];      /* beta[h][row] = x_row . g_r[h]              */
__device__ float g_t   [(size_t)Hh*BS*Ee];   /* t[h][row][e] = x @ M_h (134 MB)            */
__device__ float g_v   [(size_t)BS*Ee];      /* x @ Wv + bv                                */
__device__ float g_vals[(size_t)BS*Ee];      /* attention output, (b,s, h*64+d) layout     */

/* =====================================================================
 * M_h = SCALE * Wq_h @ Wk_h^T   (NT gemm over the contiguous e dim)
 * C[m,n] = SCALE * sum_k Wqk[m*LDW + h*1024 + k] * Wqk[n*LDW + h*1024+512 + k]
 * ===================================================================== */
__global__ __launch_bounds__(256) void mmat_kernel(const float* __restrict__ Wqk)
{
    const int h  = blockIdx.z;
    const int m0 = blockIdx.x * 128, n0 = blockIdx.y * 128;
    const int tid = threadIdx.x;
    const int tx = tid & 15, ty = tid >> 4;

    __shared__ float As[16][132];
    __shared__ float Bs[16][132];

    const float* Ab = Wqk + h * (2*Ee);        /* + c*LDW + e */
    const float* Bb2 = Wqk + h * (2*Ee) + Ee;

    float acc[8][8];
    #pragma unroll
    for (int i = 0; i < 8; i++)
        #pragma unroll
        for (int j = 0; j < 8; j++) acc[i][j] = 0.f;

    for (int kk = 0; kk < Ee; kk += 16) {
        #pragma unroll
        for (int i = 0; i < 2; i++) {
            int slot = tid + (i << 8);
            int m  = slot >> 2;
            int k4 = (slot & 3) << 2;
            float4 av = *(const float4*)(Ab  + (long)(m0 + m) * LDW + kk + k4);
            As[k4+0][m] = av.x; As[k4+1][m] = av.y; As[k4+2][m] = av.z; As[k4+3][m] = av.w;
            float4 bv = *(const float4*)(Bb2 + (long)(n0 + m) * LDW + kk + k4);
            Bs[k4+0][m] = bv.x; Bs[k4+1][m] = bv.y; Bs[k4+2][m] = bv.z; Bs[k4+3][m] = bv.w;
        }
        __syncthreads();
        #pragma unroll
        for (int k = 0; k < 16; k++) {
            float a[8], b[8];
            *(float4*)(a)     = *(const float4*)&As[k][ty*4];
            *(float4*)(a + 4) = *(const float4*)&As[k][ty*4 + 64];
            *(float4*)(b)     = *(const float4*)&Bs[k][tx*4];
            *(float4*)(b + 4) = *(const float4*)&Bs[k][tx*4 + 64];
            #pragma unroll
            for (int i = 0; i < 8; i++)
                #pragma unroll
                for (int j = 0; j < 8; j++) acc[i][j] += a[i] * b[j];
        }
        __syncthreads();
    }

    float* C = g_M + (size_t)h * Ee * Ee;
    #pragma unroll
    for (int rh = 0; rh < 2; rh++)
        #pragma unroll
        for (int i = 0; i < 4; i++) {
            int row = m0 + rh*64 + ty*4 + i;
            #pragma unroll
            for (int ch = 0; ch < 2; ch++) {
                float4 ov = make_float4(acc[rh*4+i][ch*4+0] * SCALE,
                                        acc[rh*4+i][ch*4+1] * SCALE,
                                        acc[rh*4+i][ch*4+2] * SCALE,
                                        acc[rh*4+i][ch*4+3] * SCALE);
                *(float4*)(C + (long)row * Ee + n0 + ch*64 + tx*4) = ov;
            }
        }
}

/* g_r[h*512 + c] = SCALE * sum_e Wqk[c*LDW + h*1024+512 + e] * bqk[h*1024 + e] */
__global__ void rvec_kernel(const float* __restrict__ Wqk, const float* __restrict__ bqk)
{
    int g = blockIdx.x * 256 + threadIdx.x;       /* 0..4095 */
    int h = g >> 9, c = g & 511;
    const float* wk = Wqk + (long)c * LDW + h * (2*Ee) + Ee;
    const float* bq = bqk + h * (2*Ee);
    float acc = 0.f;
    #pragma unroll 4
    for (int e = 0; e < Ee; e += 4) {
        acc += wk[e]*bq[e] + wk[e+1]*bq[e+1] + wk[e+2]*bq[e+2] + wk[e+3]*bq[e+3];
    }
    g_r[g] = acc * SCALE;
}

/* beta[h][row] = x_row . g_r[h]   (one warp per output) */
__global__ __launch_bounds__(256) void beta_kernel(const float* __restrict__ x)
{
    int w    = blockIdx.x * 8 + (threadIdx.x >> 5);   /* 0..65535 */
    int lane = threadIdx.x & 31;
    int h    = w >> 13;           /* /8192 */
    int row  = w & 8191;
    float acc = 0.f;
    #pragma unroll
    for (int i = 0; i < 4; i++) {
        int c = lane * 4 + i * 128;
        float4 xv = *(const float4*)(x   + (long)row * Ee + c);
        float4 rv = *(const float4*)(g_r + h * Ee + c);
        acc += xv.x*rv.x + xv.y*rv.y + xv.z*rv.z + xv.w*rv.w;
    }
    #pragma unroll
    for (int off = 16; off; off >>= 1) acc += __shfl_xor_sync(0xffffffffu, acc, off);
    if (!lane) g_beta[w] = acc;
}

/* =====================================================================
 * Generic fp32 SGEMM: C[z] = A @ B[z] (+ bias), 128x128x16 tiles, 8x8/thread
 * A row-major [M,K] (shared across z), B row-major [K,N], C row-major [M,N]
 * ===================================================================== */
__global__ __launch_bounds__(256) void sgemm_kernel(
    const float* __restrict__ A, const float* __restrict__ Bm,
    const float* __restrict__ bias, float* __restrict__ C,
    int Ndim, int Kdim, long strideB, long strideC)
{
    const int z = blockIdx.z;
    const float* Bz = Bm + (size_t)z * strideB;
    float*       Cz = C  + (size_t)z * strideC;
    const int m0 = blockIdx.x * 128, n0 = blockIdx.y * 128;
    const int tid = threadIdx.x;
    const int tx = tid & 15, ty = tid >> 4;

    __shared__ float As[16][132];
    __shared__ float Bs[16][128];

    float acc[8][8];
    #pragma unroll
    for (int i = 0; i < 8; i++)
        #pragma unroll
        for (int j = 0; j < 8; j++) acc[i][j] = 0.f;

    for (int kk = 0; kk < Kdim; kk += 16) {
        #pragma unroll
        for (int i = 0; i < 2; i++) {
            int slot = tid + (i << 8);
            int m  = slot >> 2;
            int k4 = (slot & 3) << 2;
            float4 av = *(const float4*)(A + (long)(m0 + m) * Kdim + kk + k4);
            As[k4+0][m] = av.x; As[k4+1][m] = av.y; As[k4+2][m] = av.z; As[k4+3][m] = av.w;
            int r  = slot >> 5;
            int c4 = (slot & 31) << 2;
            *(float4*)&Bs[r][c4] = *(const float4*)(Bz + (long)(kk + r) * Ndim + n0 + c4);
        }
        __syncthreads();
        #pragma unroll
        for (int k = 0; k < 16; k++) {
            float a[8], b[8];
            *(float4*)(a)     = *(const float4*)&As[k][ty*4];
            *(float4*)(a + 4) = *(const float4*)&As[k][ty*4 + 64];
            *(float4*)(b)     = *(const float4*)&Bs[k][tx*4];
            *(float4*)(b + 4) = *(const float4*)&Bs[k][tx*4 + 64];
            #pragma unroll
            for (int i = 0; i < 8; i++)
                #pragma unroll
                for (int j = 0; j < 8; j++) acc[i][j] += a[i] * b[j];
        }
        __syncthreads();
    }

    float b0[8] = {0,0,0,0,0,0,0,0};
    if (bias) {
        *(float4*)(b0)     = *(const float4*)(bias + n0 + tx*4);
        *(float4*)(b0 + 4) = *(const float4*)(bias + n0 + 64 + tx*4);
    }
    #pragma unroll
    for (int rh = 0; rh < 2; rh++)
        #pragma unroll
        for (int i = 0; i < 4; i++) {
            int row = m0 + rh*64 + ty*4 + i;
            #pragma unroll
            for (int ch = 0; ch < 2; ch++) {
                float4 ov = make_float4(acc[rh*4+i][ch*4+0] + b0[ch*4+0],
                                        acc[rh*4+i][ch*4+1] + b0[ch*4+1],
                                        acc[rh*4+i][ch*4+2] + b0[ch*4+2],
                                        acc[rh*4+i][ch*4+3] + b0[ch*4+3]);
                *(float4*)(Cz + (long)row * Ndim + n0 + ch*64 + tx*4) = ov;
            }
        }
}

/* =====================================================================
 * Fused flash attention (fp32, online softmax)
 * scores_eff[i,j] = t[h,row_i] . x[row_j]  + beta[h,row_j]   (scale folded)
 * 64x64 tile per CTA, 256 threads, 4x4 scores + 4x4 output per thread.
 * ===================================================================== */
__global__ __launch_bounds__(256) void attn_kernel(const float* __restrict__ x)
{
    const int qb = blockIdx.x, h = blockIdx.y, b = blockIdx.z;
    const int tid = threadIdx.x;
    const int tx = tid & 15, ty = tid >> 4;

    /* region1 (qs[32][68] + ks[32][68]) is reused as Psm[64][64]; Vsm separate */
    __shared__ float sm[2*32*68 + 64*64];
    float* qs  = sm;                 /* [32][68] transposed: qs[e][i] */
    float* ks  = sm + 32*68;         /* [32][68] transposed: ks[e][j] */
    float* Psm = sm;                 /* [64][64] */
    float* Vsm = sm + 2*32*68;       /* [64][64] */

    const long tq0 = ((long)h * BS + (long)b * Ss + qb * 64);  /* t row base      */
    const long xk0 = ((long)b * Ss);                           /* x/g_v row base  */

    float o[4][4];
    float mrow[4], lrow[4];
    #pragma unroll
    for (int r = 0; r < 4; r++) {
        mrow[r] = -1e30f; lrow[r] = 0.f;
        #pragma unroll
        for (int c = 0; c < 4; c++) o[r][c] = 0.f;
    }

    for (int kb = 0; kb < Ss/64; kb++) {
        float s[4][4];
        #pragma unroll
        for (int r = 0; r < 4; r++)
            #pragma unroll
            for (int c = 0; c < 4; c++) s[r][c] = 0.f;

        /* ---- scores: contract over E=512 in chunks of 32 ---- */
        for (int ec = 0; ec < Ee; ec += 32) {
            #pragma unroll
            for (int i = 0; i < 2; i++) {
                int slot = tid + (i << 8);
                int row = slot >> 3;
                int e4  = (slot & 7) << 2;
                float4 qv = *(const float4*)(g_t + (tq0 + row) * Ee + ec + e4);
                qs[(e4+0)*68 + row] = qv.x; qs[(e4+1)*68 + row] = qv.y;
                qs[(e4+2)*68 + row] = qv.z; qs[(e4+3)*68 + row] = qv.w;
                float4 kv = *(const float4*)(x + (xk0 + kb*64 + row) * Ee + ec + e4);
                ks[(e4+0)*68 + row] = kv.x; ks[(e4+1)*68 + row] = kv.y;
                ks[(e4+2)*68 + row] = kv.z; ks[(e4+3)*68 + row] = kv.w;
            }
            __syncthreads();
            #pragma unroll
            for (int e = 0; e < 32; e++) {
                float qa[4], ka[4];
                *(float4*)qa = *(const float4*)&qs[e*68 + ty*4];
                *(float4*)ka = *(const float4*)&ks[e*68 + tx*4];
                #pragma unroll
                for (int r = 0; r < 4; r++)
                    #pragma unroll
                    for (int c = 0; c < 4; c++) s[r][c] += qa[r] * ka[c];
            }
            __syncthreads();
        }

        /* ---- V tile (independent of softmax, load early) ---- */
        #pragma unroll
        for (int i = 0; i < 4; i++) {
            int slot = tid + (i << 8);
            int j  = slot >> 4;
            int d4 = (slot & 15) << 2;
            *(float4*)&Vsm[j*64 + d4] =
                *(const float4*)(g_v + (xk0 + kb*64 + j) * Ee + h*HDd + d4);
        }

        /* ---- online softmax ---- */
        float4 bt = *(const float4*)(g_beta + (long)h * BS + b * Ss + kb*64 + tx*4);
        float bj[4] = {bt.x, bt.y, bt.z, bt.w};
        #pragma unroll
        for (int r = 0; r < 4; r++) {
            float mx = -1e30f;
            #pragma unroll
            for (int c = 0; c < 4; c++) { s[r][c] += bj[c]; mx = fmaxf(mx, s[r][c]); }
            #pragma unroll
            for (int off = 8; off; off >>= 1)
                mx = fmaxf(mx, __shfl_xor_sync(0xffffffffu, mx, off, 16));
            float mn   = fmaxf(mrow[r], mx);
            float corr = __expf(mrow[r] - mn);
            mrow[r] = mn;
            float p[4], ps = 0.f;
            #pragma unroll
            for (int c = 0; c < 4; c++) { p[c] = __expf(s[r][c] - mn); ps += p[c]; }
            #pragma unroll
            for (int off = 8; off; off >>= 1)
                ps += __shfl_xor_sync(0xffffffffu, ps, off, 16);
            lrow[r] = lrow[r] * corr + ps;
            #pragma unroll
            for (int c = 0; c < 4; c++) o[r][c] *= corr;
            *(float4*)&Psm[(ty*4 + r)*64 + tx*4] = make_float4(p[0], p[1], p[2], p[3]);
        }
        __syncthreads();

        /* ---- O += P @ V ---- */
        #pragma unroll
        for (int jc = 0; jc < 64; jc += 4) {
            float pv[4][4], vb[4][4];
            #pragma unroll
            for (int r = 0; r < 4; r++)
                *(float4*)pv[r] = *(const float4*)&Psm[(ty*4 + r)*64 + jc];
            #pragma unroll
            for (int jj = 0; jj < 4; jj++)
                *(float4*)vb[jj] = *(const float4*)&Vsm[(jc + jj)*64 + tx*4];
            #pragma unroll
            for (int r = 0; r < 4; r++)
                #pragma unroll
                for (int jj = 0; jj < 4; jj++)
                    #pragma unroll
                    for (int c = 0; c < 4; c++)
                        o[r][c] += pv[r][jj] * vb[jj][c];
        }
        __syncthreads();
    }

    /* ---- epilogue: vals[b, s, h*64 + d] = o / l ---- */
    #pragma unroll
    for (int r = 0; r < 4; r++) {
        float inv = 1.0f / lrow[r];
        float4 ov = make_float4(o[r][0]*inv, o[r][1]*inv, o[r][2]*inv, o[r][3]*inv);
        *(float4*)(g_vals + ((long)b * Ss + qb*64 + ty*4 + r) * Ee + h*HDd + tx*4) = ov;
    }
}

/* ===================================================================== */
extern "C" void kernel_launch(void* const* d_in, const int* in_sizes, int n_in,
                              void* d_out, int out_size)
{
    const float* x   = (const float*)d_in[0];
    const float* Wqk = (const float*)d_in[1];
    const float* bqk = (const float*)d_in[2];
    const float* Wv  = (const float*)d_in[3];
    const float* bv  = (const float*)d_in[4];
    const float* Wo  = (const float*)d_in[5];
    const float* bo  = (const float*)d_in[6];
    float* out = (float*)d_out;

    void *pM, *pT, *pV, *pVals;
    cudaGetSymbolAddress(&pM,    g_M);
    cudaGetSymbolAddress(&pT,    g_t);
    cudaGetSymbolAddress(&pV,    g_v);
    cudaGetSymbolAddress(&pVals, g_vals);

    /* 1. M_h = scale * Wq_h Wk_h^T ; r_h = scale * Wk_h bq_h ; beta */
    mmat_kernel<<<dim3(4, 4, 8), 256>>>(Wqk);
    rvec_kernel<<<16, 256>>>(Wqk, bqk);
    beta_kernel<<<8192, 256>>>(x);

    /* 2. t[h] = x @ M_h  (batched over h) */
    sgemm_kernel<<<dim3(64, 4, 8), 256>>>(
        x, (const float*)pM, nullptr, (float*)pT,
        Ee, Ee, (long)Ee * Ee, (long)BS * Ee);

    /* 3. v = x @ Wv + bv */
    sgemm_kernel<<<dim3(64, 4, 1), 256>>>(
        x, Wv, bv, (float*)pV, Ee, Ee, 0, 0);

    /* 4. fused flash attention -> g_vals (b, s, h*64+d) */
    attn_kernel<<<dim3(Ss/64, Hh, Bb), 256>>>(x);

    /* 5. out = vals @ Wo + bo */
    sgemm_kernel<<<dim3(64, 4, 1), 256>>>(
        (const float*)pVals, Wo, bo, out, Ee, Ee, 0, 0);
}

// round 9
// speedup vs baseline: 4.7123x; 4.7123x over previous
#include <cuda_runtime.h>
#include <math.h>
#include <stdint.h>

#define Bb   4
#define Ss   2048
#define Ee   512
#define Hh   8
#define HDd  64
#define BS   (Bb*Ss)            /* 8192 */
#define LDW  (2*Ee*Hh)          /* 8192 */
#define SCALE 0.044194173824159216f  /* 1/sqrt(512) */

/* ---- scratch (static device globals; no runtime allocation) ---- */
__device__ float g_Mt  [(size_t)Hh*Ee*Ee];   /* Mt[h][c'][c] = scale*Wk_c'.Wq_c (8 MB)    */
__device__ float g_r   [Hh*Ee];
__device__ float g_beta[(size_t)Hh*BS];
__device__ float g_t   [(size_t)Hh*BS*Ee];   /* t[h][row][e'] (134 MB)                    */
__device__ float g_v   [(size_t)BS*Ee];      /* x @ Wv + bv                               */
__device__ float g_vT  [(size_t)BS*Ee];      /* [(b*512 + d)][s]                          */
__device__ float g_vals[(size_t)BS*Ee];      /* attention output (b,s, h*64+d)            */

/* =============================== helpers =============================== */
__device__ __forceinline__ uint32_t f2tf(float f){
    uint32_t r; asm("cvt.rna.tf32.f32 %0, %1;" : "=r"(r) : "f"(f)); return r;
}
__device__ __forceinline__ void mma8(float c[4], const uint32_t a[4], const uint32_t b[2]){
    asm volatile("mma.sync.aligned.m16n8k8.row.col.f32.tf32.tf32.f32 "
        "{%0,%1,%2,%3}, {%4,%5,%6,%7}, {%8,%9}, {%0,%1,%2,%3};"
        : "+f"(c[0]), "+f"(c[1]), "+f"(c[2]), "+f"(c[3])
        : "r"(a[0]), "r"(a[1]), "r"(a[2]), "r"(a[3]), "r"(b[0]), "r"(b[1]));
}

/* =====================================================================
 * tf32 NT GEMM via mma.sync: C[z][m][n] = alpha * sum_k A[m][k]*B[n][k] (+bias[n])
 * CTA 128x128, 8 warps (4m x 2n), warp tile 32x64, K-slab 32.
 * ===================================================================== */
__global__ __launch_bounds__(256) void tfgemm_nt(
    const float* __restrict__ A, long lda, long sAz,
    const float* __restrict__ B, long ldb, long sBz,
    const float* __restrict__ bias, float* __restrict__ C, long ldc, long sCz,
    int Kdim, float alpha)
{
    __shared__ uint32_t As[128*36];
    __shared__ uint32_t Bs[128*36];
    const int tid = threadIdx.x;
    const int lane = tid & 31, wid = tid >> 5;
    const int wm = wid & 3, wn = wid >> 2;
    const int m0 = blockIdx.x*128, n0 = blockIdx.y*128, z = blockIdx.z;
    A += (size_t)z * sAz; B += (size_t)z * sBz; C += (size_t)z * sCz;

    float c[2][8][4];
    #pragma unroll
    for (int mt = 0; mt < 2; mt++)
        #pragma unroll
        for (int nt = 0; nt < 8; nt++)
            #pragma unroll
            for (int i = 0; i < 4; i++) c[mt][nt][i] = 0.f;

    float4 ra[4], rb[4];
    #pragma unroll
    for (int i = 0; i < 4; i++) {
        int s = tid + i*256, r = s >> 3, k4 = (s & 7) * 4;
        ra[i] = *(const float4*)(A + (size_t)(m0 + r)*lda + k4);
        rb[i] = *(const float4*)(B + (size_t)(n0 + r)*ldb + k4);
    }

    for (int kk = 0; kk < Kdim; kk += 32) {
        __syncthreads();
        #pragma unroll
        for (int i = 0; i < 4; i++) {
            int s = tid + i*256, r = s >> 3, k4 = (s & 7) * 4;
            uint32_t* pa = &As[r*36 + k4];
            pa[0]=f2tf(ra[i].x); pa[1]=f2tf(ra[i].y); pa[2]=f2tf(ra[i].z); pa[3]=f2tf(ra[i].w);
            uint32_t* pb = &Bs[r*36 + k4];
            pb[0]=f2tf(rb[i].x); pb[1]=f2tf(rb[i].y); pb[2]=f2tf(rb[i].z); pb[3]=f2tf(rb[i].w);
        }
        __syncthreads();
        if (kk + 32 < Kdim) {
            #pragma unroll
            for (int i = 0; i < 4; i++) {
                int s = tid + i*256, r = s >> 3, k4 = (s & 7) * 4;
                ra[i] = *(const float4*)(A + (size_t)(m0 + r)*lda + kk + 32 + k4);
                rb[i] = *(const float4*)(B + (size_t)(n0 + r)*ldb + kk + 32 + k4);
            }
        }
        #pragma unroll
        for (int kb = 0; kb < 32; kb += 8) {
            uint32_t af[2][4];
            #pragma unroll
            for (int mt = 0; mt < 2; mt++) {
                int r = wm*32 + mt*16 + (lane >> 2);
                af[mt][0] = As[r*36       + kb + (lane & 3)];
                af[mt][1] = As[(r+8)*36   + kb + (lane & 3)];
                af[mt][2] = As[r*36       + kb + (lane & 3) + 4];
                af[mt][3] = As[(r+8)*36   + kb + (lane & 3) + 4];
            }
            #pragma unroll
            for (int nt = 0; nt < 8; nt++) {
                int nr = wn*64 + nt*8 + (lane >> 2);
                uint32_t bf[2];
                bf[0] = Bs[nr*36 + kb + (lane & 3)];
                bf[1] = Bs[nr*36 + kb + (lane & 3) + 4];
                mma8(c[0][nt], af[0], bf);
                mma8(c[1][nt], af[1], bf);
            }
        }
    }

    #pragma unroll
    for (int mt = 0; mt < 2; mt++)
        #pragma unroll
        for (int nt = 0; nt < 8; nt++)
            #pragma unroll
            for (int hf = 0; hf < 2; hf++) {
                int row = m0 + wm*32 + mt*16 + hf*8 + (lane >> 2);
                int col = n0 + wn*64 + nt*8 + (lane & 3)*2;
                float2 v;
                v.x = alpha * c[mt][nt][hf*2+0];
                v.y = alpha * c[mt][nt][hf*2+1];
                if (bias) { v.x += bias[col]; v.y += bias[col+1]; }
                *(float2*)(C + (size_t)row*ldc + col) = v;
            }
}

__global__ void rvec_kernel(const float* __restrict__ Wqk, const float* __restrict__ bqk)
{
    int g = blockIdx.x * 256 + threadIdx.x;
    int h = g >> 9, cc = g & 511;
    const float* wk = Wqk + (long)cc * LDW + h * (2*Ee) + Ee;
    const float* bq = bqk + h * (2*Ee);
    float acc = 0.f;
    #pragma unroll 4
    for (int e = 0; e < Ee; e += 4)
        acc += wk[e]*bq[e] + wk[e+1]*bq[e+1] + wk[e+2]*bq[e+2] + wk[e+3]*bq[e+3];
    g_r[g] = acc * SCALE;
}

__global__ __launch_bounds__(256) void beta_kernel(const float* __restrict__ x)
{
    int w    = blockIdx.x * 8 + (threadIdx.x >> 5);
    int lane = threadIdx.x & 31;
    int h    = w >> 13;
    int row  = w & 8191;
    float acc = 0.f;
    #pragma unroll
    for (int i = 0; i < 4; i++) {
        int cc = lane * 4 + i * 128;
        float4 xv = *(const float4*)(x   + (long)row * Ee + cc);
        float4 rv = *(const float4*)(g_r + h * Ee + cc);
        acc += xv.x*rv.x + xv.y*rv.y + xv.z*rv.z + xv.w*rv.w;
    }
    #pragma unroll
    for (int off = 16; off; off >>= 1) acc += __shfl_xor_sync(0xffffffffu, acc, off);
    if (!lane) g_beta[w] = acc;
}

/* ====== fp32 SGEMM (proven) for v-GEMM and out-GEMM ====== */
__global__ __launch_bounds__(256) void sgemm_kernel(
    const float* __restrict__ A, const float* __restrict__ Bm,
    const float* __restrict__ bias, float* __restrict__ C,
    int Ndim, int Kdim)
{
    const int m0 = blockIdx.x * 128, n0 = blockIdx.y * 128;
    const int tid = threadIdx.x;
    const int tx = tid & 15, ty = tid >> 4;

    __shared__ float As[16][132];
    __shared__ float Bs[16][128];

    float acc[8][8];
    #pragma unroll
    for (int i = 0; i < 8; i++)
        #pragma unroll
        for (int j = 0; j < 8; j++) acc[i][j] = 0.f;

    for (int kk = 0; kk < Kdim; kk += 16) {
        #pragma unroll
        for (int i = 0; i < 2; i++) {
            int slot = tid + (i << 8);
            int m  = slot >> 2;
            int k4 = (slot & 3) << 2;
            float4 av = *(const float4*)(A + (long)(m0 + m) * Kdim + kk + k4);
            As[k4+0][m] = av.x; As[k4+1][m] = av.y; As[k4+2][m] = av.z; As[k4+3][m] = av.w;
            int r  = slot >> 5;
            int c4 = (slot & 31) << 2;
            *(float4*)&Bs[r][c4] = *(const float4*)(Bm + (long)(kk + r) * Ndim + n0 + c4);
        }
        __syncthreads();
        #pragma unroll
        for (int k = 0; k < 16; k++) {
            float a[8], b[8];
            *(float4*)(a)     = *(const float4*)&As[k][ty*4];
            *(float4*)(a + 4) = *(const float4*)&As[k][ty*4 + 64];
            *(float4*)(b)     = *(const float4*)&Bs[k][tx*4];
            *(float4*)(b + 4) = *(const float4*)&Bs[k][tx*4 + 64];
            #pragma unroll
            for (int i = 0; i < 8; i++)
                #pragma unroll
                for (int j = 0; j < 8; j++) acc[i][j] += a[i] * b[j];
        }
        __syncthreads();
    }

    float b0[8] = {0,0,0,0,0,0,0,0};
    if (bias) {
        *(float4*)(b0)     = *(const float4*)(bias + n0 + tx*4);
        *(float4*)(b0 + 4) = *(const float4*)(bias + n0 + 64 + tx*4);
    }
    #pragma unroll
    for (int rh = 0; rh < 2; rh++)
        #pragma unroll
        for (int i = 0; i < 4; i++) {
            int row = m0 + rh*64 + ty*4 + i;
            #pragma unroll
            for (int ch = 0; ch < 2; ch++) {
                float4 ov = make_float4(acc[rh*4+i][ch*4+0] + b0[ch*4+0],
                                        acc[rh*4+i][ch*4+1] + b0[ch*4+1],
                                        acc[rh*4+i][ch*4+2] + b0[ch*4+2],
                                        acc[rh*4+i][ch*4+3] + b0[ch*4+3]);
                *(float4*)(C + (long)row * Ndim + n0 + ch*64 + tx*4) = ov;
            }
        }
}

/* g_v[(b*2048+s)*512 + c] -> g_vT[(b*512+c)*2048 + s] */
__global__ void vtrans_kernel()
{
    __shared__ float ts[32][33];
    const int b  = blockIdx.z;
    const int s0 = blockIdx.x * 32, c0 = blockIdx.y * 32;
    for (int i = threadIdx.y; i < 32; i += 8)
        ts[i][threadIdx.x] = g_v[((size_t)b*Ss + s0 + i)*Ee + c0 + threadIdx.x];
    __syncthreads();
    for (int i = threadIdx.y; i < 32; i += 8)
        g_vT[((size_t)b*Ee + c0 + i)*Ss + s0 + threadIdx.x] = ts[threadIdx.x][i];
}

/* =====================================================================
 * Fused attention (mma.sync tf32): CTA = (qb, h, b), 128 q-rows.
 * Scores S = t . x^T per 128-key tile (K=512), unnormalized softmax,
 * O += P @ V^T with register accumulators across 16 key tiles.
 * SMEM: bsm 0..512 | lsm 512..1536 | As 1536(+18432) | Bs 19968(+18432)
 *       | Ps 38400(+67584) | Vs 105984(+33792)  total 139776
 * ===================================================================== */
#define AT_SMEM 139776
__global__ __launch_bounds__(256, 1) void attn_kernel(const float* __restrict__ x)
{
    extern __shared__ char sma[];
    float*    bsm = (float*)(sma);
    float*    lsm = (float*)(sma + 512);
    uint32_t* As  = (uint32_t*)(sma + 1536);
    uint32_t* Bs  = (uint32_t*)(sma + 19968);
    uint32_t* Ps  = (uint32_t*)(sma + 38400);
    uint32_t* Vs  = (uint32_t*)(sma + 105984);

    const int tid = threadIdx.x, lane = tid & 31, wid = tid >> 5;
    const int wm = wid & 3, wn = wid >> 2;
    const int qb = blockIdx.x, h = blockIdx.y, b = blockIdx.z;

    const size_t tb0 = ((size_t)h*BS + (size_t)b*Ss + qb*128);   /* g_t row base  */
    const size_t xb0 = (size_t)b*Ss;                              /* x row base    */
    const size_t vb0 = (size_t)b*Ee + h*HDd;                      /* g_vT row base */

    float co[2][4][4];
    #pragma unroll
    for (int mt = 0; mt < 2; mt++)
        #pragma unroll
        for (int nt = 0; nt < 4; nt++)
            #pragma unroll
            for (int i = 0; i < 4; i++) co[mt][nt][i] = 0.f;
    float lrun[4] = {0.f, 0.f, 0.f, 0.f};

    for (int kt = 0; kt < 16; kt++) {
        __syncthreads();                 /* everyone done with bsm/Ps/Vs of kt-1 */
        if (tid < 128)
            bsm[tid] = g_beta[(size_t)h*BS + (size_t)b*Ss + kt*128 + tid];

        float cs[2][8][4];
        #pragma unroll
        for (int mt = 0; mt < 2; mt++)
            #pragma unroll
            for (int nt = 0; nt < 8; nt++)
                #pragma unroll
                for (int i = 0; i < 4; i++) cs[mt][nt][i] = 0.f;

        /* ---- scores over E=512 in 16 slabs of 32 ---- */
        float4 ra[4], rb[4];
        #pragma unroll
        for (int i = 0; i < 4; i++) {
            int s = tid + i*256, r = s >> 3, k4 = (s & 7) * 4;
            ra[i] = *(const float4*)(g_t + (tb0 + r)*Ee + k4);
            rb[i] = *(const float4*)(x + (xb0 + kt*128 + r)*Ee + k4);
        }
        for (int j = 0; j < 16; j++) {
            __syncthreads();
            #pragma unroll
            for (int i = 0; i < 4; i++) {
                int s = tid + i*256, r = s >> 3, k4 = (s & 7) * 4;
                uint32_t* pa = &As[r*36 + k4];
                pa[0]=f2tf(ra[i].x); pa[1]=f2tf(ra[i].y); pa[2]=f2tf(ra[i].z); pa[3]=f2tf(ra[i].w);
                uint32_t* pb = &Bs[r*36 + k4];
                pb[0]=f2tf(rb[i].x); pb[1]=f2tf(rb[i].y); pb[2]=f2tf(rb[i].z); pb[3]=f2tf(rb[i].w);
            }
            __syncthreads();
            if (j < 15) {
                int ec = (j + 1) * 32;
                #pragma unroll
                for (int i = 0; i < 4; i++) {
                    int s = tid + i*256, r = s >> 3, k4 = (s & 7) * 4;
                    ra[i] = *(const float4*)(g_t + (tb0 + r)*Ee + ec + k4);
                    rb[i] = *(const float4*)(x + (xb0 + kt*128 + r)*Ee + ec + k4);
                }
            }
            #pragma unroll
            for (int kb = 0; kb < 32; kb += 8) {
                uint32_t af[2][4];
                #pragma unroll
                for (int mt = 0; mt < 2; mt++) {
                    int r = wm*32 + mt*16 + (lane >> 2);
                    af[mt][0] = As[r*36     + kb + (lane & 3)];
                    af[mt][1] = As[(r+8)*36 + kb + (lane & 3)];
                    af[mt][2] = As[r*36     + kb + (lane & 3) + 4];
                    af[mt][3] = As[(r+8)*36 + kb + (lane & 3) + 4];
                }
                #pragma unroll
                for (int nt = 0; nt < 8; nt++) {
                    int nr = wn*64 + nt*8 + (lane >> 2);
                    uint32_t bf[2];
                    bf[0] = Bs[nr*36 + kb + (lane & 3)];
                    bf[1] = Bs[nr*36 + kb + (lane & 3) + 4];
                    mma8(cs[0][nt], af[0], bf);
                    mma8(cs[1][nt], af[1], bf);
                }
            }
        }

        /* ---- unnormalized softmax; P -> SMEM (tf32) ---- */
        float part[4] = {0.f, 0.f, 0.f, 0.f};
        #pragma unroll
        for (int mt = 0; mt < 2; mt++)
            #pragma unroll
            for (int nt = 0; nt < 8; nt++) {
                int col = wn*64 + nt*8 + (lane & 3)*2;
                int r   = wm*32 + mt*16 + (lane >> 2);
                float p0 = __expf(cs[mt][nt][0] + bsm[col]);
                float p1 = __expf(cs[mt][nt][1] + bsm[col+1]);
                float p2 = __expf(cs[mt][nt][2] + bsm[col]);
                float p3 = __expf(cs[mt][nt][3] + bsm[col+1]);
                part[mt*2+0] += p0 + p1;
                part[mt*2+1] += p2 + p3;
                *(uint2*)&Ps[r*132 + col]     = make_uint2(f2tf(p0), f2tf(p1));
                *(uint2*)&Ps[(r+8)*132 + col] = make_uint2(f2tf(p2), f2tf(p3));
            }
        #pragma unroll
        for (int i = 0; i < 4; i++) {
            part[i] += __shfl_xor_sync(0xffffffffu, part[i], 1);
            part[i] += __shfl_xor_sync(0xffffffffu, part[i], 2);
            lrun[i] += part[i];
        }

        /* ---- V^T tile: Vs[d][j] (64 x 128), tf32 ---- */
        #pragma unroll
        for (int i = 0; i < 8; i++) {
            int s = tid + i*256, d = s >> 5, j4 = (s & 31) * 4;
            float4 v = *(const float4*)(g_vT + (vb0 + d)*Ss + kt*128 + j4);
            uint32_t* pv = &Vs[d*132 + j4];
            pv[0]=f2tf(v.x); pv[1]=f2tf(v.y); pv[2]=f2tf(v.z); pv[3]=f2tf(v.w);
        }
        __syncthreads();

        /* ---- O += P @ V^T, K = 128 ---- */
        #pragma unroll
        for (int kb = 0; kb < 128; kb += 8) {
            uint32_t af[2][4];
            #pragma unroll
            for (int mt = 0; mt < 2; mt++) {
                int r = wm*32 + mt*16 + (lane >> 2);
                af[mt][0] = Ps[r*132     + kb + (lane & 3)];
                af[mt][1] = Ps[(r+8)*132 + kb + (lane & 3)];
                af[mt][2] = Ps[r*132     + kb + (lane & 3) + 4];
                af[mt][3] = Ps[(r+8)*132 + kb + (lane & 3) + 4];
            }
            #pragma unroll
            for (int nt = 0; nt < 4; nt++) {
                int d = wn*32 + nt*8 + (lane >> 2);
                uint32_t bf[2];
                bf[0] = Vs[d*132 + kb + (lane & 3)];
                bf[1] = Vs[d*132 + kb + (lane & 3) + 4];
                mma8(co[0][nt], af[0], bf);
                mma8(co[1][nt], af[1], bf);
            }
        }
    }

    /* ---- epilogue: combine row sums across the two warp columns ---- */
    if ((lane & 3) == 0) {
        #pragma unroll
        for (int mt = 0; mt < 2; mt++)
            #pragma unroll
            for (int hf = 0; hf < 2; hf++)
                lsm[wn*128 + wm*32 + mt*16 + hf*8 + (lane >> 2)] = lrun[mt*2 + hf];
    }
    __syncthreads();
    #pragma unroll
    for (int mt = 0; mt < 2; mt++)
        #pragma unroll
        for (int hf = 0; hf < 2; hf++) {
            int row = wm*32 + mt*16 + hf*8 + (lane >> 2);
            float inv = 1.0f / (lsm[row] + lsm[128 + row]);
            #pragma unroll
            for (int nt = 0; nt < 4; nt++) {
                int col = wn*32 + nt*8 + (lane & 3)*2;
                float2 v;
                v.x = co[mt][nt][hf*2+0] * inv;
                v.y = co[mt][nt][hf*2+1] * inv;
                *(float2*)(g_vals + ((size_t)b*Ss + qb*128 + row)*Ee + h*HDd + col) = v;
            }
        }
}

/* ===================================================================== */
extern "C" void kernel_launch(void* const* d_in, const int* in_sizes, int n_in,
                              void* d_out, int out_size)
{
    const float* x   = (const float*)d_in[0];
    const float* Wqk = (const float*)d_in[1];
    const float* bqk = (const float*)d_in[2];
    const float* Wv  = (const float*)d_in[3];
    const float* bv  = (const float*)d_in[4];
    const float* Wo  = (const float*)d_in[5];
    const float* bo  = (const float*)d_in[6];
    float* out = (float*)d_out;

    cudaFuncSetAttribute(attn_kernel, cudaFuncAttributeMaxDynamicSharedMemorySize, AT_SMEM);

    void *pMt, *pT, *pV, *pVals;
    cudaGetSymbolAddress(&pMt,   g_Mt);
    cudaGetSymbolAddress(&pT,    g_t);
    cudaGetSymbolAddress(&pV,    g_v);
    cudaGetSymbolAddress(&pVals, g_vals);

    /* 1. Mt[h] = SCALE * Wk_rows . Wq_rows^T  (NT, contract over e) */
    tfgemm_nt<<<dim3(4, 4, 8), 256>>>(
        Wqk + Ee, LDW, 2*Ee,            /* A = Wk rows, per-h offset 1024 */
        Wqk,      LDW, 2*Ee,            /* B = Wq rows                     */
        nullptr, (float*)pMt, Ee, (long)Ee*Ee, Ee, SCALE);

    rvec_kernel<<<16, 256>>>(Wqk, bqk);
    beta_kernel<<<8192, 256>>>(x);

    /* 2. t[h] = x @ M_h : NT with B = Mt[h] ([c'][c], K-major) */
    tfgemm_nt<<<dim3(64, 4, 8), 256>>>(
        x, Ee, 0,
        (const float*)pMt, Ee, (long)Ee*Ee,
        nullptr, (float*)pT, Ee, (long)BS*Ee, Ee, 1.0f);

    /* 3. v = x @ Wv + bv (fp32) ; transpose for attention B-operand */
    sgemm_kernel<<<dim3(64, 4), 256>>>(x, Wv, bv, (float*)pV, Ee, Ee);
    vtrans_kernel<<<dim3(64, 16, 4), dim3(32, 8)>>>();

    /* 4. fused attention (mma.sync tf32) */
    attn_kernel<<<dim3(16, Hh, Bb), 256, AT_SMEM>>>(x);

    /* 5. out = vals @ Wo + bo (fp32) */
    sgemm_kernel<<<dim3(64, 4), 256>>>((const float*)pVals, Wo, bo, out, Ee, Ee);
}

// round 10
// speedup vs baseline: 5.3962x; 1.1451x over previous
#include <cuda_runtime.h>
#include <math.h>
#include <stdint.h>

#define Bb   4
#define Ss   2048
#define Ee   512
#define Hh   8
#define HDd  64
#define BS   (Bb*Ss)            /* 8192 */
#define LDW  (2*Ee*Hh)          /* 8192 */
#define SCALE 0.044194173824159216f  /* 1/sqrt(512) */

/* ---- scratch (static device globals; no runtime allocation) ---- */
__device__ uint32_t g_Mtu [(size_t)Hh*Ee*Ee];  /* tf32 Mt[h][c'][c] (8 MB)          */
__device__ float    g_r   [Hh*Ee];
__device__ float    g_beta[(size_t)Hh*BS];
__device__ uint32_t g_xt  [(size_t)BS*Ee];     /* tf32 x (17 MB)                    */
__device__ uint32_t g_tu  [(size_t)Hh*BS*Ee];  /* tf32 t[h][row][e'] (134 MB)       */
__device__ float    g_v   [(size_t)BS*Ee];     /* x @ Wv + bv                       */
__device__ uint32_t g_vTu [(size_t)BS*Ee];     /* tf32 [(b*512+d)][s]               */
__device__ float    g_vals[(size_t)BS*Ee];     /* attention output (b,s, h*64+d)    */

/* =============================== helpers =============================== */
__device__ __forceinline__ uint32_t f2tf(float f){
    uint32_t r; asm("cvt.rna.tf32.f32 %0, %1;" : "=r"(r) : "f"(f)); return r;
}
__device__ __forceinline__ void mma8(float c[4], const uint32_t a[4], const uint32_t b[2]){
    asm volatile("mma.sync.aligned.m16n8k8.row.col.f32.tf32.tf32.f32 "
        "{%0,%1,%2,%3}, {%4,%5,%6,%7}, {%8,%9}, {%0,%1,%2,%3};"
        : "+f"(c[0]), "+f"(c[1]), "+f"(c[2]), "+f"(c[3])
        : "r"(a[0]), "r"(a[1]), "r"(a[2]), "r"(a[3]), "r"(b[0]), "r"(b[1]));
}
__device__ __forceinline__ uint32_t smem_u32(const void* p){
    uint32_t a;
    asm("{ .reg .u64 t; cvta.to.shared.u64 t, %1; cvt.u32.u64 %0, t; }" : "=r"(a) : "l"(p));
    return a;
}
__device__ __forceinline__ void cpa16(uint32_t dst, const void* src){
    asm volatile("cp.async.cg.shared.global [%0], [%1], 16;" :: "r"(dst), "l"(src) : "memory");
}
#define CP_COMMIT() asm volatile("cp.async.commit_group;" ::: "memory")
#define CP_WAIT0()  asm volatile("cp.async.wait_group 0;" ::: "memory")
#define CP_WAIT1()  asm volatile("cp.async.wait_group 1;" ::: "memory")

/* x -> tf32 copy */
__global__ void xcvt_kernel(const float* __restrict__ x)
{
    size_t i = ((size_t)blockIdx.x * 256 + threadIdx.x) * 4;
    float4 v = *(const float4*)(x + i);
    uint4 o; o.x = f2tf(v.x); o.y = f2tf(v.y); o.z = f2tf(v.z); o.w = f2tf(v.w);
    *(uint4*)(g_xt + i) = o;
}

/* =====================================================================
 * tf32 NT GEMM, fp32 inputs (cvt at STS), tf32 uint32 output.
 * Used only for the small M-precompute. CTA 128x128, warp 32x64, K-slab 32.
 * ===================================================================== */
__global__ __launch_bounds__(256) void tfgemm_nt(
    const float* __restrict__ A, long lda, long sAz,
    const float* __restrict__ B, long ldb, long sBz,
    uint32_t* __restrict__ C, long ldc, long sCz,
    int Kdim, float alpha)
{
    __shared__ uint32_t As[128*36];
    __shared__ uint32_t Bs[128*36];
    const int tid = threadIdx.x;
    const int lane = tid & 31, wid = tid >> 5;
    const int wm = wid & 3, wn = wid >> 2;
    const int m0 = blockIdx.x*128, n0 = blockIdx.y*128, z = blockIdx.z;
    A += (size_t)z * sAz; B += (size_t)z * sBz; C += (size_t)z * sCz;

    float c[2][8][4];
    #pragma unroll
    for (int mt = 0; mt < 2; mt++)
        #pragma unroll
        for (int nt = 0; nt < 8; nt++)
            #pragma unroll
            for (int i = 0; i < 4; i++) c[mt][nt][i] = 0.f;

    float4 ra[4], rb[4];
    #pragma unroll
    for (int i = 0; i < 4; i++) {
        int s = tid + i*256, r = s >> 3, k4 = (s & 7) * 4;
        ra[i] = *(const float4*)(A + (size_t)(m0 + r)*lda + k4);
        rb[i] = *(const float4*)(B + (size_t)(n0 + r)*ldb + k4);
    }

    for (int kk = 0; kk < Kdim; kk += 32) {
        __syncthreads();
        #pragma unroll
        for (int i = 0; i < 4; i++) {
            int s = tid + i*256, r = s >> 3, k4 = (s & 7) * 4;
            uint32_t* pa = &As[r*36 + k4];
            pa[0]=f2tf(ra[i].x); pa[1]=f2tf(ra[i].y); pa[2]=f2tf(ra[i].z); pa[3]=f2tf(ra[i].w);
            uint32_t* pb = &Bs[r*36 + k4];
            pb[0]=f2tf(rb[i].x); pb[1]=f2tf(rb[i].y); pb[2]=f2tf(rb[i].z); pb[3]=f2tf(rb[i].w);
        }
        __syncthreads();
        if (kk + 32 < Kdim) {
            #pragma unroll
            for (int i = 0; i < 4; i++) {
                int s = tid + i*256, r = s >> 3, k4 = (s & 7) * 4;
                ra[i] = *(const float4*)(A + (size_t)(m0 + r)*lda + kk + 32 + k4);
                rb[i] = *(const float4*)(B + (size_t)(n0 + r)*ldb + kk + 32 + k4);
            }
        }
        #pragma unroll
        for (int kb = 0; kb < 32; kb += 8) {
            uint32_t af[2][4];
            #pragma unroll
            for (int mt = 0; mt < 2; mt++) {
                int r = wm*32 + mt*16 + (lane >> 2);
                af[mt][0] = As[r*36       + kb + (lane & 3)];
                af[mt][1] = As[(r+8)*36   + kb + (lane & 3)];
                af[mt][2] = As[r*36       + kb + (lane & 3) + 4];
                af[mt][3] = As[(r+8)*36   + kb + (lane & 3) + 4];
            }
            #pragma unroll
            for (int nt = 0; nt < 8; nt++) {
                int nr = wn*64 + nt*8 + (lane >> 2);
                uint32_t bf[2];
                bf[0] = Bs[nr*36 + kb + (lane & 3)];
                bf[1] = Bs[nr*36 + kb + (lane & 3) + 4];
                mma8(c[0][nt], af[0], bf);
                mma8(c[1][nt], af[1], bf);
            }
        }
    }

    #pragma unroll
    for (int mt = 0; mt < 2; mt++)
        #pragma unroll
        for (int nt = 0; nt < 8; nt++)
            #pragma unroll
            for (int hf = 0; hf < 2; hf++) {
                int row = m0 + wm*32 + mt*16 + hf*8 + (lane >> 2);
                int col = n0 + wn*64 + nt*8 + (lane & 3)*2;
                uint2 v;
                v.x = f2tf(alpha * c[mt][nt][hf*2+0]);
                v.y = f2tf(alpha * c[mt][nt][hf*2+1]);
                *(uint2*)(C + (size_t)row*ldc + col) = v;
            }
}

/* =====================================================================
 * Pipelined tf32 NT GEMM, tf32 uint32 in/out, cp.async 3-stage.
 * Used for the big t-GEMM. 2 CTAs/SM.
 * ===================================================================== */
#define TGP_SMEM (2*3*4608*4)   /* 110592 */
__global__ __launch_bounds__(256, 2) void tfgemm_p(
    const uint32_t* __restrict__ A, long lda, long sAz,
    const uint32_t* __restrict__ B, long ldb, long sBz,
    uint32_t* __restrict__ C, long ldc, long sCz, int Kdim)
{
    extern __shared__ uint32_t shp[];
    uint32_t* As = shp;
    uint32_t* Bs = shp + 3*4608;
    const uint32_t sA = smem_u32(As), sB = smem_u32(Bs);
    const int tid = threadIdx.x;
    const int lane = tid & 31, wid = tid >> 5;
    const int wm = wid & 3, wn = wid >> 2;
    const int m0 = blockIdx.x*128, n0 = blockIdx.y*128, z = blockIdx.z;
    A += (size_t)z * sAz; B += (size_t)z * sBz; C += (size_t)z * sCz;

    float c[2][8][4];
    #pragma unroll
    for (int mt = 0; mt < 2; mt++)
        #pragma unroll
        for (int nt = 0; nt < 8; nt++)
            #pragma unroll
            for (int i = 0; i < 4; i++) c[mt][nt][i] = 0.f;

    const int nslab = Kdim / 32;
    #pragma unroll
    for (int st = 0; st < 2; st++) {
        int ec = st * 32;
        #pragma unroll
        for (int i = 0; i < 4; i++) {
            int s = tid + i*256, r = s >> 3, k4 = (s & 7) * 4;
            cpa16(sA + (uint32_t)(st*4608 + r*36 + k4)*4, A + (size_t)(m0 + r)*lda + ec + k4);
            cpa16(sB + (uint32_t)(st*4608 + r*36 + k4)*4, B + (size_t)(n0 + r)*ldb + ec + k4);
        }
        CP_COMMIT();
    }

    for (int j = 0; j < nslab; j++) {
        if (j < nslab - 1) { CP_WAIT1(); } else { CP_WAIT0(); }
        __syncthreads();
        const uint32_t* Aj = As + (j % 3) * 4608;
        const uint32_t* Bj = Bs + (j % 3) * 4608;
        #pragma unroll
        for (int kb = 0; kb < 32; kb += 8) {
            uint32_t af[2][4];
            #pragma unroll
            for (int mt = 0; mt < 2; mt++) {
                int r = wm*32 + mt*16 + (lane >> 2);
                af[mt][0] = Aj[r*36     + kb + (lane & 3)];
                af[mt][1] = Aj[(r+8)*36 + kb + (lane & 3)];
                af[mt][2] = Aj[r*36     + kb + (lane & 3) + 4];
                af[mt][3] = Aj[(r+8)*36 + kb + (lane & 3) + 4];
            }
            #pragma unroll
            for (int nt = 0; nt < 8; nt++) {
                int nr = wn*64 + nt*8 + (lane >> 2);
                uint32_t bf[2];
                bf[0] = Bj[nr*36 + kb + (lane & 3)];
                bf[1] = Bj[nr*36 + kb + (lane & 3) + 4];
                mma8(c[0][nt], af[0], bf);
                mma8(c[1][nt], af[1], bf);
            }
        }
        if (j + 2 < nslab) {
            int ec = (j + 2) * 32, bi = (j + 2) % 3;
            #pragma unroll
            for (int i = 0; i < 4; i++) {
                int s = tid + i*256, r = s >> 3, k4 = (s & 7) * 4;
                cpa16(sA + (uint32_t)(bi*4608 + r*36 + k4)*4, A + (size_t)(m0 + r)*lda + ec + k4);
                cpa16(sB + (uint32_t)(bi*4608 + r*36 + k4)*4, B + (size_t)(n0 + r)*ldb + ec + k4);
            }
            CP_COMMIT();
        }
    }

    #pragma unroll
    for (int mt = 0; mt < 2; mt++)
        #pragma unroll
        for (int nt = 0; nt < 8; nt++)
            #pragma unroll
            for (int hf = 0; hf < 2; hf++) {
                int row = m0 + wm*32 + mt*16 + hf*8 + (lane >> 2);
                int col = n0 + wn*64 + nt*8 + (lane & 3)*2;
                uint2 v;
                v.x = f2tf(c[mt][nt][hf*2+0]);
                v.y = f2tf(c[mt][nt][hf*2+1]);
                *(uint2*)(C + (size_t)row*ldc + col) = v;
            }
}

__global__ void rvec_kernel(const float* __restrict__ Wqk, const float* __restrict__ bqk)
{
    int g = blockIdx.x * 256 + threadIdx.x;
    int h = g >> 9, cc = g & 511;
    const float* wk = Wqk + (long)cc * LDW + h * (2*Ee) + Ee;
    const float* bq = bqk + h * (2*Ee);
    float acc = 0.f;
    #pragma unroll 4
    for (int e = 0; e < Ee; e += 4)
        acc += wk[e]*bq[e] + wk[e+1]*bq[e+1] + wk[e+2]*bq[e+2] + wk[e+3]*bq[e+3];
    g_r[g] = acc * SCALE;
}

__global__ __launch_bounds__(256) void beta_kernel(const float* __restrict__ x)
{
    int w    = blockIdx.x * 8 + (threadIdx.x >> 5);
    int lane = threadIdx.x & 31;
    int h    = w >> 13;
    int row  = w & 8191;
    float acc = 0.f;
    #pragma unroll
    for (int i = 0; i < 4; i++) {
        int cc = lane * 4 + i * 128;
        float4 xv = *(const float4*)(x   + (long)row * Ee + cc);
        float4 rv = *(const float4*)(g_r + h * Ee + cc);
        acc += xv.x*rv.x + xv.y*rv.y + xv.z*rv.z + xv.w*rv.w;
    }
    #pragma unroll
    for (int off = 16; off; off >>= 1) acc += __shfl_xor_sync(0xffffffffu, acc, off);
    if (!lane) g_beta[w] = acc;
}

/* ====== fp32 SGEMM (proven) for v-GEMM and out-GEMM ====== */
__global__ __launch_bounds__(256) void sgemm_kernel(
    const float* __restrict__ A, const float* __restrict__ Bm,
    const float* __restrict__ bias, float* __restrict__ C,
    int Ndim, int Kdim)
{
    const int m0 = blockIdx.x * 128, n0 = blockIdx.y * 128;
    const int tid = threadIdx.x;
    const int tx = tid & 15, ty = tid >> 4;

    __shared__ float As[16][132];
    __shared__ float Bs[16][128];

    float acc[8][8];
    #pragma unroll
    for (int i = 0; i < 8; i++)
        #pragma unroll
        for (int j = 0; j < 8; j++) acc[i][j] = 0.f;

    for (int kk = 0; kk < Kdim; kk += 16) {
        #pragma unroll
        for (int i = 0; i < 2; i++) {
            int slot = tid + (i << 8);
            int m  = slot >> 2;
            int k4 = (slot & 3) << 2;
            float4 av = *(const float4*)(A + (long)(m0 + m) * Kdim + kk + k4);
            As[k4+0][m] = av.x; As[k4+1][m] = av.y; As[k4+2][m] = av.z; As[k4+3][m] = av.w;
            int r  = slot >> 5;
            int c4 = (slot & 31) << 2;
            *(float4*)&Bs[r][c4] = *(const float4*)(Bm + (long)(kk + r) * Ndim + n0 + c4);
        }
        __syncthreads();
        #pragma unroll
        for (int k = 0; k < 16; k++) {
            float a[8], b[8];
            *(float4*)(a)     = *(const float4*)&As[k][ty*4];
            *(float4*)(a + 4) = *(const float4*)&As[k][ty*4 + 64];
            *(float4*)(b)     = *(const float4*)&Bs[k][tx*4];
            *(float4*)(b + 4) = *(const float4*)&Bs[k][tx*4 + 64];
            #pragma unroll
            for (int i = 0; i < 8; i++)
                #pragma unroll
                for (int j = 0; j < 8; j++) acc[i][j] += a[i] * b[j];
        }
        __syncthreads();
    }

    float b0[8] = {0,0,0,0,0,0,0,0};
    if (bias) {
        *(float4*)(b0)     = *(const float4*)(bias + n0 + tx*4);
        *(float4*)(b0 + 4) = *(const float4*)(bias + n0 + 64 + tx*4);
    }
    #pragma unroll
    for (int rh = 0; rh < 2; rh++)
        #pragma unroll
        for (int i = 0; i < 4; i++) {
            int row = m0 + rh*64 + ty*4 + i;
            #pragma unroll
            for (int ch = 0; ch < 2; ch++) {
                float4 ov = make_float4(acc[rh*4+i][ch*4+0] + b0[ch*4+0],
                                        acc[rh*4+i][ch*4+1] + b0[ch*4+1],
                                        acc[rh*4+i][ch*4+2] + b0[ch*4+2],
                                        acc[rh*4+i][ch*4+3] + b0[ch*4+3]);
                *(float4*)(C + (long)row * Ndim + n0 + ch*64 + tx*4) = ov;
            }
        }
}

/* g_v[(b*2048+s)*512 + c] -> g_vTu[(b*512+c)*2048 + s] (tf32) */
__global__ void vtrans_kernel()
{
    __shared__ float ts[32][33];
    const int b  = blockIdx.z;
    const int s0 = blockIdx.x * 32, c0 = blockIdx.y * 32;
    for (int i = threadIdx.y; i < 32; i += 8)
        ts[i][threadIdx.x] = g_v[((size_t)b*Ss + s0 + i)*Ee + c0 + threadIdx.x];
    __syncthreads();
    for (int i = threadIdx.y; i < 32; i += 8)
        g_vTu[((size_t)b*Ee + c0 + i)*Ss + s0 + threadIdx.x] = f2tf(ts[threadIdx.x][i]);
}

/* =====================================================================
 * Fused attention (mma.sync tf32, cp.async 3-stage pipelined).
 * CTA = (qb, h, b), 128 q-rows; 16 key tiles of 128; K=512 scores.
 * SMEM map (bytes): bsm 0 | lsm 512 | As 1536 (3x18432) | Bs 56832 (3x18432)
 *   | Ps 112128 (67584) | Vs 179712 (33792)  -> total 213504
 * ===================================================================== */
#define AT_SMEM 213504
__global__ __launch_bounds__(256, 1) void attn_kernel()
{
    extern __shared__ char sma[];
    float*    bsm = (float*)(sma);
    float*    lsm = (float*)(sma + 512);
    uint32_t* As  = (uint32_t*)(sma + 1536);
    uint32_t* Bs  = (uint32_t*)(sma + 56832);
    uint32_t* Ps  = (uint32_t*)(sma + 112128);
    uint32_t* Vs  = (uint32_t*)(sma + 179712);
    const uint32_t sA = smem_u32(As), sB = smem_u32(Bs), sV = smem_u32(Vs);

    const int tid = threadIdx.x, lane = tid & 31, wid = tid >> 5;
    const int wm = wid & 3, wn = wid >> 2;
    const int qb = blockIdx.x, h = blockIdx.y, b = blockIdx.z;

    const uint32_t* At = g_tu  + ((size_t)h*BS + (size_t)b*Ss + qb*128)*Ee;
    const uint32_t* Bx = g_xt  + ((size_t)b*Ss)*Ee;
    const uint32_t* Vt = g_vTu + ((size_t)b*Ee + h*HDd)*Ss;

    float co[2][4][4];
    #pragma unroll
    for (int mt = 0; mt < 2; mt++)
        #pragma unroll
        for (int nt = 0; nt < 4; nt++)
            #pragma unroll
            for (int i = 0; i < 4; i++) co[mt][nt][i] = 0.f;
    float lrun[4] = {0.f, 0.f, 0.f, 0.f};

    for (int kt = 0; kt < 16; kt++) {
        __syncthreads();          /* prev PV readers done with Ps/Vs; bsm safe */
        if (tid < 128)
            bsm[tid] = g_beta[(size_t)h*BS + (size_t)b*Ss + kt*128 + tid];

        float cs[2][8][4];
        #pragma unroll
        for (int mt = 0; mt < 2; mt++)
            #pragma unroll
            for (int nt = 0; nt < 8; nt++)
                #pragma unroll
                for (int i = 0; i < 4; i++) cs[mt][nt][i] = 0.f;

        const uint32_t* Bk = Bx + (size_t)kt*128*Ee;

        /* ---- scores pipeline: prologue (slabs 0,1) ---- */
        #pragma unroll
        for (int st = 0; st < 2; st++) {
            int ec = st * 32;
            #pragma unroll
            for (int i = 0; i < 4; i++) {
                int s = tid + i*256, r = s >> 3, k4 = (s & 7) * 4;
                cpa16(sA + (uint32_t)(st*4608 + r*36 + k4)*4, At + (size_t)r*Ee + ec + k4);
                cpa16(sB + (uint32_t)(st*4608 + r*36 + k4)*4, Bk + (size_t)r*Ee + ec + k4);
            }
            CP_COMMIT();
        }

        for (int j = 0; j < 16; j++) {
            if (j < 15) { CP_WAIT1(); } else { CP_WAIT0(); }
            __syncthreads();
            const uint32_t* Aj = As + (j % 3) * 4608;
            const uint32_t* Bj = Bs + (j % 3) * 4608;
            #pragma unroll
            for (int kb = 0; kb < 32; kb += 8) {
                uint32_t af[2][4];
                #pragma unroll
                for (int mt = 0; mt < 2; mt++) {
                    int r = wm*32 + mt*16 + (lane >> 2);
                    af[mt][0] = Aj[r*36     + kb + (lane & 3)];
                    af[mt][1] = Aj[(r+8)*36 + kb + (lane & 3)];
                    af[mt][2] = Aj[r*36     + kb + (lane & 3) + 4];
                    af[mt][3] = Aj[(r+8)*36 + kb + (lane & 3) + 4];
                }
                #pragma unroll
                for (int nt = 0; nt < 8; nt++) {
                    int nr = wn*64 + nt*8 + (lane >> 2);
                    uint32_t bf[2];
                    bf[0] = Bj[nr*36 + kb + (lane & 3)];
                    bf[1] = Bj[nr*36 + kb + (lane & 3) + 4];
                    mma8(cs[0][nt], af[0], bf);
                    mma8(cs[1][nt], af[1], bf);
                }
            }
            if (j < 14) {
                int ec = (j + 2) * 32, bi = (j + 2) % 3;
                #pragma unroll
                for (int i = 0; i < 4; i++) {
                    int s = tid + i*256, r = s >> 3, k4 = (s & 7) * 4;
                    cpa16(sA + (uint32_t)(bi*4608 + r*36 + k4)*4, At + (size_t)r*Ee + ec + k4);
                    cpa16(sB + (uint32_t)(bi*4608 + r*36 + k4)*4, Bk + (size_t)r*Ee + ec + k4);
                }
                CP_COMMIT();
            }
        }

        /* ---- V tile async load (overlaps softmax math) ---- */
        #pragma unroll
        for (int i = 0; i < 8; i++) {
            int s = tid + i*256, d = s >> 5, j4 = (s & 31) * 4;
            cpa16(sV + (uint32_t)(d*132 + j4)*4, Vt + (size_t)d*Ss + kt*128 + j4);
        }
        CP_COMMIT();

        /* ---- unnormalized softmax; P -> SMEM (tf32) ---- */
        float part[4] = {0.f, 0.f, 0.f, 0.f};
        #pragma unroll
        for (int mt = 0; mt < 2; mt++)
            #pragma unroll
            for (int nt = 0; nt < 8; nt++) {
                int col = wn*64 + nt*8 + (lane & 3)*2;
                int r   = wm*32 + mt*16 + (lane >> 2);
                float p0 = __expf(cs[mt][nt][0] + bsm[col]);
                float p1 = __expf(cs[mt][nt][1] + bsm[col+1]);
                float p2 = __expf(cs[mt][nt][2] + bsm[col]);
                float p3 = __expf(cs[mt][nt][3] + bsm[col+1]);
                part[mt*2+0] += p0 + p1;
                part[mt*2+1] += p2 + p3;
                *(uint2*)&Ps[r*132 + col]     = make_uint2(f2tf(p0), f2tf(p1));
                *(uint2*)&Ps[(r+8)*132 + col] = make_uint2(f2tf(p2), f2tf(p3));
            }
        #pragma unroll
        for (int i = 0; i < 4; i++) {
            part[i] += __shfl_xor_sync(0xffffffffu, part[i], 1);
            part[i] += __shfl_xor_sync(0xffffffffu, part[i], 2);
            lrun[i] += part[i];
        }

        CP_WAIT0();
        __syncthreads();

        /* ---- O += P @ V^T, K = 128 ---- */
        #pragma unroll
        for (int kb = 0; kb < 128; kb += 8) {
            uint32_t af[2][4];
            #pragma unroll
            for (int mt = 0; mt < 2; mt++) {
                int r = wm*32 + mt*16 + (lane >> 2);
                af[mt][0] = Ps[r*132     + kb + (lane & 3)];
                af[mt][1] = Ps[(r+8)*132 + kb + (lane & 3)];
                af[mt][2] = Ps[r*132     + kb + (lane & 3) + 4];
                af[mt][3] = Ps[(r+8)*132 + kb + (lane & 3) + 4];
            }
            #pragma unroll
            for (int nt = 0; nt < 4; nt++) {
                int d = wn*32 + nt*8 + (lane >> 2);
                uint32_t bf[2];
                bf[0] = Vs[d*132 + kb + (lane & 3)];
                bf[1] = Vs[d*132 + kb + (lane & 3) + 4];
                mma8(co[0][nt], af[0], bf);
                mma8(co[1][nt], af[1], bf);
            }
        }
    }

    /* ---- epilogue: combine row sums across the two warp columns ---- */
    if ((lane & 3) == 0) {
        #pragma unroll
        for (int mt = 0; mt < 2; mt++)
            #pragma unroll
            for (int hf = 0; hf < 2; hf++)
                lsm[wn*128 + wm*32 + mt*16 + hf*8 + (lane >> 2)] = lrun[mt*2 + hf];
    }
    __syncthreads();
    #pragma unroll
    for (int mt = 0; mt < 2; mt++)
        #pragma unroll
        for (int hf = 0; hf < 2; hf++) {
            int row = wm*32 + mt*16 + hf*8 + (lane >> 2);
            float inv = 1.0f / (lsm[row] + lsm[128 + row]);
            #pragma unroll
            for (int nt = 0; nt < 4; nt++) {
                int col = wn*32 + nt*8 + (lane & 3)*2;
                float2 v;
                v.x = co[mt][nt][hf*2+0] * inv;
                v.y = co[mt][nt][hf*2+1] * inv;
                *(float2*)(g_vals + ((size_t)blockIdx.z*Ss + blockIdx.x*128 + row)*Ee
                           + blockIdx.y*HDd + col) = v;
            }
        }
}

/* ===================================================================== */
extern "C" void kernel_launch(void* const* d_in, const int* in_sizes, int n_in,
                              void* d_out, int out_size)
{
    const float* x   = (const float*)d_in[0];
    const float* Wqk = (const float*)d_in[1];
    const float* bqk = (const float*)d_in[2];
    const float* Wv  = (const float*)d_in[3];
    const float* bv  = (const float*)d_in[4];
    const float* Wo  = (const float*)d_in[5];
    const float* bo  = (const float*)d_in[6];
    float* out = (float*)d_out;

    cudaFuncSetAttribute(attn_kernel, cudaFuncAttributeMaxDynamicSharedMemorySize, AT_SMEM);
    cudaFuncSetAttribute(tfgemm_p,    cudaFuncAttributeMaxDynamicSharedMemorySize, TGP_SMEM);

    void *pMtu, *pXt, *pTu, *pV, *pVals;
    cudaGetSymbolAddress(&pMtu,  g_Mtu);
    cudaGetSymbolAddress(&pXt,   g_xt);
    cudaGetSymbolAddress(&pTu,   g_tu);
    cudaGetSymbolAddress(&pV,    g_v);
    cudaGetSymbolAddress(&pVals, g_vals);

    /* 0. x -> tf32 */
    xcvt_kernel<<<BS*Ee/1024, 256>>>(x);

    /* 1. Mt[h] = SCALE * Wk . Wq^T  (tf32 out) */
    tfgemm_nt<<<dim3(4, 4, 8), 256>>>(
        Wqk + Ee, LDW, 2*Ee,
        Wqk,      LDW, 2*Ee,
        (uint32_t*)pMtu, Ee, (long)Ee*Ee, Ee, SCALE);

    rvec_kernel<<<16, 256>>>(Wqk, bqk);
    beta_kernel<<<8192, 256>>>(x);

    /* 2. t[h] = x @ M_h  (pipelined, tf32 in/out) */
    tfgemm_p<<<dim3(64, 4, 8), 256, TGP_SMEM>>>(
        (const uint32_t*)pXt, Ee, 0,
        (const uint32_t*)pMtu, Ee, (long)Ee*Ee,
        (uint32_t*)pTu, Ee, (long)BS*Ee, Ee);

    /* 3. v = x @ Wv + bv (fp32) ; transpose to tf32 */
    sgemm_kernel<<<dim3(64, 4), 256>>>(x, Wv, bv, (float*)pV, Ee, Ee);
    vtrans_kernel<<<dim3(64, 16, 4), dim3(32, 8)>>>();

    /* 4. fused attention (pipelined mma.sync tf32) */
    attn_kernel<<<dim3(16, Hh, Bb), 256, AT_SMEM>>>();

    /* 5. out = vals @ Wo + bo (fp32) */
    sgemm_kernel<<<dim3(64, 4), 256>>>((const float*)pVals, Wo, bo, out, Ee, Ee);
}

// round 11
// speedup vs baseline: 5.9038x; 1.0941x over previous
#include <cuda_runtime.h>
#include <math.h>
#include <stdint.h>

#define Bb   4
#define Ss   2048
#define Ee   512
#define Hh   8
#define HDd  64
#define BS   (Bb*Ss)            /* 8192 */
#define LDW  (2*Ee*Hh)          /* 8192 */
#define SCALE 0.044194173824159216f  /* 1/sqrt(512) */

/* ---- scratch (static device globals; no runtime allocation) ---- */
__device__ uint32_t g_Mtu  [(size_t)Hh*Ee*Ee];  /* tf32 Mt[h][c'][c] (8 MB)         */
__device__ float    g_r    [Hh*Ee];
__device__ float    g_beta [(size_t)Hh*BS];
__device__ uint32_t g_xt   [(size_t)BS*Ee];     /* tf32 x (17 MB)                   */
__device__ uint32_t g_tu   [(size_t)Hh*BS*Ee];  /* tf32 t[h][row][e'] (134 MB)      */
__device__ uint32_t g_WvT  [Ee*Ee];             /* tf32 Wv^T [d][c]                 */
__device__ uint32_t g_WoT  [Ee*Ee];             /* tf32 Wo^T [e][k]                 */
__device__ uint32_t g_vTu  [(size_t)BS*Ee];     /* tf32 v^T [(b*512+d)][s]          */
__device__ uint32_t g_valsu[(size_t)BS*Ee];     /* tf32 attention out (b,s,h*64+d)  */

/* =============================== helpers =============================== */
__device__ __forceinline__ uint32_t f2tf(float f){
    uint32_t r; asm("cvt.rna.tf32.f32 %0, %1;" : "=r"(r) : "f"(f)); return r;
}
__device__ __forceinline__ void mma8(float c[4], const uint32_t a[4], const uint32_t b[2]){
    asm volatile("mma.sync.aligned.m16n8k8.row.col.f32.tf32.tf32.f32 "
        "{%0,%1,%2,%3}, {%4,%5,%6,%7}, {%8,%9}, {%0,%1,%2,%3};"
        : "+f"(c[0]), "+f"(c[1]), "+f"(c[2]), "+f"(c[3])
        : "r"(a[0]), "r"(a[1]), "r"(a[2]), "r"(a[3]), "r"(b[0]), "r"(b[1]));
}
__device__ __forceinline__ uint32_t smem_u32(const void* p){
    uint32_t a;
    asm("{ .reg .u64 t; cvta.to.shared.u64 t, %1; cvt.u32.u64 %0, t; }" : "=r"(a) : "l"(p));
    return a;
}
__device__ __forceinline__ void cpa16(uint32_t dst, const void* src){
    asm volatile("cp.async.cg.shared.global [%0], [%1], 16;" :: "r"(dst), "l"(src) : "memory");
}
#define CP_COMMIT() asm volatile("cp.async.commit_group;" ::: "memory")
#define CP_WAIT0()  asm volatile("cp.async.wait_group 0;" ::: "memory")
#define CP_WAIT1()  asm volatile("cp.async.wait_group 1;" ::: "memory")
#define CP_WAIT2()  asm volatile("cp.async.wait_group 2;" ::: "memory")

/* x -> tf32 copy */
__global__ void xcvt_kernel(const float* __restrict__ x)
{
    size_t i = ((size_t)blockIdx.x * 256 + threadIdx.x) * 4;
    float4 v = *(const float4*)(x + i);
    uint4 o; o.x = f2tf(v.x); o.y = f2tf(v.y); o.z = f2tf(v.z); o.w = f2tf(v.w);
    *(uint4*)(g_xt + i) = o;
}

/* W[512x512] fp32 -> WT[n][k] tf32 */
__global__ void wtrans_kernel(const float* __restrict__ W, uint32_t* __restrict__ WT)
{
    __shared__ float ts[32][33];
    const int k0 = blockIdx.x * 32, n0 = blockIdx.y * 32;
    for (int i = threadIdx.y; i < 32; i += 8)
        ts[i][threadIdx.x] = W[(k0 + i) * Ee + n0 + threadIdx.x];
    __syncthreads();
    for (int i = threadIdx.y; i < 32; i += 8)
        WT[(n0 + i) * Ee + k0 + threadIdx.x] = f2tf(ts[threadIdx.x][i]);
}

/* =====================================================================
 * tf32 NT GEMM, fp32 inputs (cvt at STS), tf32 out. For M-precompute only.
 * ===================================================================== */
__global__ __launch_bounds__(256) void tfgemm_nt(
    const float* __restrict__ A, long lda, long sAz,
    const float* __restrict__ B, long ldb, long sBz,
    uint32_t* __restrict__ C, long ldc, long sCz,
    int Kdim, float alpha)
{
    __shared__ uint32_t As[128*36];
    __shared__ uint32_t Bs[128*36];
    const int tid = threadIdx.x;
    const int lane = tid & 31, wid = tid >> 5;
    const int wm = wid & 3, wn = wid >> 2;
    const int m0 = blockIdx.x*128, n0 = blockIdx.y*128, z = blockIdx.z;
    A += (size_t)z * sAz; B += (size_t)z * sBz; C += (size_t)z * sCz;

    float c[2][8][4];
    #pragma unroll
    for (int mt = 0; mt < 2; mt++)
        #pragma unroll
        for (int nt = 0; nt < 8; nt++)
            #pragma unroll
            for (int i = 0; i < 4; i++) c[mt][nt][i] = 0.f;

    float4 ra[4], rb[4];
    #pragma unroll
    for (int i = 0; i < 4; i++) {
        int s = tid + i*256, r = s >> 3, k4 = (s & 7) * 4;
        ra[i] = *(const float4*)(A + (size_t)(m0 + r)*lda + k4);
        rb[i] = *(const float4*)(B + (size_t)(n0 + r)*ldb + k4);
    }

    for (int kk = 0; kk < Kdim; kk += 32) {
        __syncthreads();
        #pragma unroll
        for (int i = 0; i < 4; i++) {
            int s = tid + i*256, r = s >> 3, k4 = (s & 7) * 4;
            uint32_t* pa = &As[r*36 + k4];
            pa[0]=f2tf(ra[i].x); pa[1]=f2tf(ra[i].y); pa[2]=f2tf(ra[i].z); pa[3]=f2tf(ra[i].w);
            uint32_t* pb = &Bs[r*36 + k4];
            pb[0]=f2tf(rb[i].x); pb[1]=f2tf(rb[i].y); pb[2]=f2tf(rb[i].z); pb[3]=f2tf(rb[i].w);
        }
        __syncthreads();
        if (kk + 32 < Kdim) {
            #pragma unroll
            for (int i = 0; i < 4; i++) {
                int s = tid + i*256, r = s >> 3, k4 = (s & 7) * 4;
                ra[i] = *(const float4*)(A + (size_t)(m0 + r)*lda + kk + 32 + k4);
                rb[i] = *(const float4*)(B + (size_t)(n0 + r)*ldb + kk + 32 + k4);
            }
        }
        #pragma unroll
        for (int kb = 0; kb < 32; kb += 8) {
            uint32_t af[2][4];
            #pragma unroll
            for (int mt = 0; mt < 2; mt++) {
                int r = wm*32 + mt*16 + (lane >> 2);
                af[mt][0] = As[r*36       + kb + (lane & 3)];
                af[mt][1] = As[(r+8)*36   + kb + (lane & 3)];
                af[mt][2] = As[r*36       + kb + (lane & 3) + 4];
                af[mt][3] = As[(r+8)*36   + kb + (lane & 3) + 4];
            }
            #pragma unroll
            for (int nt = 0; nt < 8; nt++) {
                int nr = wn*64 + nt*8 + (lane >> 2);
                uint32_t bf[2];
                bf[0] = Bs[nr*36 + kb + (lane & 3)];
                bf[1] = Bs[nr*36 + kb + (lane & 3) + 4];
                mma8(c[0][nt], af[0], bf);
                mma8(c[1][nt], af[1], bf);
            }
        }
    }

    #pragma unroll
    for (int mt = 0; mt < 2; mt++)
        #pragma unroll
        for (int nt = 0; nt < 8; nt++)
            #pragma unroll
            for (int hf = 0; hf < 2; hf++) {
                int row = m0 + wm*32 + mt*16 + hf*8 + (lane >> 2);
                int col = n0 + wn*64 + nt*8 + (lane & 3)*2;
                uint2 v;
                v.x = f2tf(alpha * c[mt][nt][hf*2+0]);
                v.y = f2tf(alpha * c[mt][nt][hf*2+1]);
                *(uint2*)(C + (size_t)row*ldc + col) = v;
            }
}

/* =====================================================================
 * Pipelined tf32 NT GEMM, tf32 in, cp.async 3-stage, 2 CTAs/SM.
 * Optional per-row bias (biasM), per-col bias (biasN), fp32 or tf32 out.
 * Serves: t-GEMM, v^T-GEMM, out-GEMM.
 * ===================================================================== */
#define TGP_SMEM (2*3*4608*4)   /* 110592 */
__global__ __launch_bounds__(256, 2) void tfgemm_p2(
    const uint32_t* __restrict__ A, long lda, long sAz,
    const uint32_t* __restrict__ B, long ldb, long sBz,
    const float* __restrict__ biasM, const float* __restrict__ biasN,
    void* __restrict__ Cv, long ldc, long sCz, int Kdim, int out_fp32)
{
    extern __shared__ uint32_t shp[];
    uint32_t* As = shp;
    uint32_t* Bs = shp + 3*4608;
    const uint32_t sA = smem_u32(As), sB = smem_u32(Bs);
    const int tid = threadIdx.x;
    const int lane = tid & 31, wid = tid >> 5;
    const int wm = wid & 3, wn = wid >> 2;
    const int m0 = blockIdx.x*128, n0 = blockIdx.y*128, z = blockIdx.z;
    A += (size_t)z * sAz; B += (size_t)z * sBz;

    float c[2][8][4];
    #pragma unroll
    for (int mt = 0; mt < 2; mt++)
        #pragma unroll
        for (int nt = 0; nt < 8; nt++)
            #pragma unroll
            for (int i = 0; i < 4; i++) c[mt][nt][i] = 0.f;

    const int nslab = Kdim / 32;
    #pragma unroll
    for (int st = 0; st < 2; st++) {
        int ec = st * 32;
        #pragma unroll
        for (int i = 0; i < 4; i++) {
            int s = tid + i*256, r = s >> 3, k4 = (s & 7) * 4;
            cpa16(sA + (uint32_t)(st*4608 + r*36 + k4)*4, A + (size_t)(m0 + r)*lda + ec + k4);
            cpa16(sB + (uint32_t)(st*4608 + r*36 + k4)*4, B + (size_t)(n0 + r)*ldb + ec + k4);
        }
        CP_COMMIT();
    }

    for (int j = 0; j < nslab; j++) {
        if (j < nslab - 1) { CP_WAIT1(); } else { CP_WAIT0(); }
        __syncthreads();
        const uint32_t* Aj = As + (j % 3) * 4608;
        const uint32_t* Bj = Bs + (j % 3) * 4608;
        #pragma unroll
        for (int kb = 0; kb < 32; kb += 8) {
            uint32_t af[2][4];
            #pragma unroll
            for (int mt = 0; mt < 2; mt++) {
                int r = wm*32 + mt*16 + (lane >> 2);
                af[mt][0] = Aj[r*36     + kb + (lane & 3)];
                af[mt][1] = Aj[(r+8)*36 + kb + (lane & 3)];
                af[mt][2] = Aj[r*36     + kb + (lane & 3) + 4];
                af[mt][3] = Aj[(r+8)*36 + kb + (lane & 3) + 4];
            }
            #pragma unroll
            for (int nt = 0; nt < 8; nt++) {
                int nr = wn*64 + nt*8 + (lane >> 2);
                uint32_t bf[2];
                bf[0] = Bj[nr*36 + kb + (lane & 3)];
                bf[1] = Bj[nr*36 + kb + (lane & 3) + 4];
                mma8(c[0][nt], af[0], bf);
                mma8(c[1][nt], af[1], bf);
            }
        }
        if (j + 2 < nslab) {
            int ec = (j + 2) * 32, bi = (j + 2) % 3;
            #pragma unroll
            for (int i = 0; i < 4; i++) {
                int s = tid + i*256, r = s >> 3, k4 = (s & 7) * 4;
                cpa16(sA + (uint32_t)(bi*4608 + r*36 + k4)*4, A + (size_t)(m0 + r)*lda + ec + k4);
                cpa16(sB + (uint32_t)(bi*4608 + r*36 + k4)*4, B + (size_t)(n0 + r)*ldb + ec + k4);
            }
            CP_COMMIT();
        }
    }

    #pragma unroll
    for (int mt = 0; mt < 2; mt++)
        #pragma unroll
        for (int nt = 0; nt < 8; nt++)
            #pragma unroll
            for (int hf = 0; hf < 2; hf++) {
                int row = m0 + wm*32 + mt*16 + hf*8 + (lane >> 2);
                int col = n0 + wn*64 + nt*8 + (lane & 3)*2;
                float bm = biasM ? biasM[row] : 0.f;
                float vx = c[mt][nt][hf*2+0] + bm;
                float vy = c[mt][nt][hf*2+1] + bm;
                if (biasN) { vx += biasN[col]; vy += biasN[col+1]; }
                size_t off = (size_t)z*sCz + (size_t)row*ldc + col;
                if (out_fp32) {
                    float2 o; o.x = vx; o.y = vy;
                    *(float2*)((float*)Cv + off) = o;
                } else {
                    uint2 o; o.x = f2tf(vx); o.y = f2tf(vy);
                    *(uint2*)((uint32_t*)Cv + off) = o;
                }
            }
}

__global__ void rvec_kernel(const float* __restrict__ Wqk, const float* __restrict__ bqk)
{
    int g = blockIdx.x * 256 + threadIdx.x;
    int h = g >> 9, cc = g & 511;
    const float* wk = Wqk + (long)cc * LDW + h * (2*Ee) + Ee;
    const float* bq = bqk + h * (2*Ee);
    float acc = 0.f;
    #pragma unroll 4
    for (int e = 0; e < Ee; e += 4)
        acc += wk[e]*bq[e] + wk[e+1]*bq[e+1] + wk[e+2]*bq[e+2] + wk[e+3]*bq[e+3];
    g_r[g] = acc * SCALE;
}

__global__ __launch_bounds__(256) void beta_kernel(const float* __restrict__ x)
{
    int w    = blockIdx.x * 8 + (threadIdx.x >> 5);
    int lane = threadIdx.x & 31;
    int h    = w >> 13;
    int row  = w & 8191;
    float acc = 0.f;
    #pragma unroll
    for (int i = 0; i < 4; i++) {
        int cc = lane * 4 + i * 128;
        float4 xv = *(const float4*)(x   + (long)row * Ee + cc);
        float4 rv = *(const float4*)(g_r + h * Ee + cc);
        acc += xv.x*rv.x + xv.y*rv.y + xv.z*rv.z + xv.w*rv.w;
    }
    #pragma unroll
    for (int off = 16; off; off >>= 1) acc += __shfl_xor_sync(0xffffffffu, acc, off);
    if (!lane) g_beta[w] = acc;
}

/* =====================================================================
 * Fused attention (mma.sync tf32, cp.async pipelined ACROSS key tiles).
 * CTA = (qb, h, b), 128 q-rows; 16 key tiles of 128; K=512 scores.
 * SMEM map (bytes): bsm 0 | lsm 512 | As 1536 (3x18432) | Bs 56832 (3x18432)
 *   | Ps 112128 (67584) | Vs 179712 (33792)  -> total 213504
 * ===================================================================== */
#define AT_SMEM 213504
__global__ __launch_bounds__(256, 1) void attn_kernel()
{
    extern __shared__ char sma[];
    float*    bsm = (float*)(sma);
    float*    lsm = (float*)(sma + 512);
    uint32_t* As  = (uint32_t*)(sma + 1536);
    uint32_t* Bs  = (uint32_t*)(sma + 56832);
    uint32_t* Ps  = (uint32_t*)(sma + 112128);
    uint32_t* Vs  = (uint32_t*)(sma + 179712);
    const uint32_t sA = smem_u32(As), sB = smem_u32(Bs), sV = smem_u32(Vs);

    const int tid = threadIdx.x, lane = tid & 31, wid = tid >> 5;
    const int wm = wid & 3, wn = wid >> 2;
    const int qb = blockIdx.x, h = blockIdx.y, b = blockIdx.z;

    const uint32_t* At = g_tu  + ((size_t)h*BS + (size_t)b*Ss + qb*128)*Ee;
    const uint32_t* Bx = g_xt  + ((size_t)b*Ss)*Ee;
    const uint32_t* Vt = g_vTu + ((size_t)b*Ee + h*HDd)*Ss;

    float co[2][4][4];
    #pragma unroll
    for (int mt = 0; mt < 2; mt++)
        #pragma unroll
        for (int nt = 0; nt < 4; nt++)
            #pragma unroll
            for (int i = 0; i < 4; i++) co[mt][nt][i] = 0.f;
    float lrun[4] = {0.f, 0.f, 0.f, 0.f};

    /* prologue: slabs 0,1 of kt=0 */
    #pragma unroll
    for (int st = 0; st < 2; st++) {
        int ec = st * 32;
        #pragma unroll
        for (int i = 0; i < 4; i++) {
            int s = tid + i*256, r = s >> 3, k4 = (s & 7) * 4;
            cpa16(sA + (uint32_t)(st*4608 + r*36 + k4)*4, At + (size_t)r*Ee + ec + k4);
            cpa16(sB + (uint32_t)(st*4608 + r*36 + k4)*4, Bx + (size_t)r*Ee + ec + k4);
        }
        CP_COMMIT();
    }

    for (int kt = 0; kt < 16; kt++) {
        __syncthreads();              /* PV(kt-1) done: Ps/Vs/bsm free */
        if (tid < 128)
            bsm[tid] = g_beta[(size_t)h*BS + (size_t)b*Ss + kt*128 + tid];

        /* V tile async — has the entire score phase to arrive */
        #pragma unroll
        for (int i = 0; i < 8; i++) {
            int s = tid + i*256, d = s >> 5, j4 = (s & 31) * 4;
            cpa16(sV + (uint32_t)(d*132 + j4)*4, Vt + (size_t)d*Ss + kt*128 + j4);
        }
        CP_COMMIT();

        float cs[2][8][4];
        #pragma unroll
        for (int mt = 0; mt < 2; mt++)
            #pragma unroll
            for (int nt = 0; nt < 8; nt++)
                #pragma unroll
                for (int i = 0; i < 4; i++) cs[mt][nt][i] = 0.f;

        const uint32_t* Bk = Bx + (size_t)kt*128*Ee;

        for (int j = 0; j < 16; j++) {
            if (j < 2) { CP_WAIT2(); } else { CP_WAIT1(); }
            __syncthreads();
            const uint32_t* Aj = As + (j % 3) * 4608;
            const uint32_t* Bj = Bs + (j % 3) * 4608;
            #pragma unroll
            for (int kb = 0; kb < 32; kb += 8) {
                uint32_t af[2][4];
                #pragma unroll
                for (int mt = 0; mt < 2; mt++) {
                    int r = wm*32 + mt*16 + (lane >> 2);
                    af[mt][0] = Aj[r*36     + kb + (lane & 3)];
                    af[mt][1] = Aj[(r+8)*36 + kb + (lane & 3)];
                    af[mt][2] = Aj[r*36     + kb + (lane & 3) + 4];
                    af[mt][3] = Aj[(r+8)*36 + kb + (lane & 3) + 4];
                }
                #pragma unroll
                for (int nt = 0; nt < 8; nt++) {
                    int nr = wn*64 + nt*8 + (lane >> 2);
                    uint32_t bf[2];
                    bf[0] = Bj[nr*36 + kb + (lane & 3)];
                    bf[1] = Bj[nr*36 + kb + (lane & 3) + 4];
                    mma8(cs[0][nt], af[0], bf);
                    mma8(cs[1][nt], af[1], bf);
                }
            }
            if (j < 14) {
                int ec = (j + 2) * 32, bi = (j + 2) % 3;
                #pragma unroll
                for (int i = 0; i < 4; i++) {
                    int s = tid + i*256, r = s >> 3, k4 = (s & 7) * 4;
                    cpa16(sA + (uint32_t)(bi*4608 + r*36 + k4)*4, At + (size_t)r*Ee + ec + k4);
                    cpa16(sB + (uint32_t)(bi*4608 + r*36 + k4)*4, Bk + (size_t)r*Ee + ec + k4);
                }
                CP_COMMIT();
            }
        }
        __syncthreads();              /* all warps done reading buf0/buf1 */

        /* keep the pipe full: prefetch slabs 0,1 of kt+1 during softmax+PV */
        if (kt < 15) {
            const uint32_t* Bk2 = Bx + (size_t)(kt+1)*128*Ee;
            #pragma unroll
            for (int st = 0; st < 2; st++) {
                int ec = st * 32;
                #pragma unroll
                for (int i = 0; i < 4; i++) {
                    int s = tid + i*256, r = s >> 3, k4 = (s & 7) * 4;
                    cpa16(sA + (uint32_t)(st*4608 + r*36 + k4)*4, At  + (size_t)r*Ee + ec + k4);
                    cpa16(sB + (uint32_t)(st*4608 + r*36 + k4)*4, Bk2 + (size_t)r*Ee + ec + k4);
                }
                CP_COMMIT();
            }
        }

        /* ---- unnormalized softmax; P -> SMEM (tf32) ---- */
        float part[4] = {0.f, 0.f, 0.f, 0.f};
        #pragma unroll
        for (int mt = 0; mt < 2; mt++)
            #pragma unroll
            for (int nt = 0; nt < 8; nt++) {
                int col = wn*64 + nt*8 + (lane & 3)*2;
                int r   = wm*32 + mt*16 + (lane >> 2);
                float p0 = __expf(cs[mt][nt][0] + bsm[col]);
                float p1 = __expf(cs[mt][nt][1] + bsm[col+1]);
                float p2 = __expf(cs[mt][nt][2] + bsm[col]);
                float p3 = __expf(cs[mt][nt][3] + bsm[col+1]);
                part[mt*2+0] += p0 + p1;
                part[mt*2+1] += p2 + p3;
                *(uint2*)&Ps[r*132 + col]     = make_uint2(f2tf(p0), f2tf(p1));
                *(uint2*)&Ps[(r+8)*132 + col] = make_uint2(f2tf(p2), f2tf(p3));
            }
        #pragma unroll
        for (int i = 0; i < 4; i++) {
            part[i] += __shfl_xor_sync(0xffffffffu, part[i], 1);
            part[i] += __shfl_xor_sync(0xffffffffu, part[i], 2);
            lrun[i] += part[i];
        }

        if (kt < 15) { CP_WAIT2(); } else { CP_WAIT0(); }   /* V done */
        __syncthreads();              /* V + Ps visible */

        /* ---- O += P @ V^T, K = 128 ---- */
        #pragma unroll
        for (int kb = 0; kb < 128; kb += 8) {
            uint32_t af[2][4];
            #pragma unroll
            for (int mt = 0; mt < 2; mt++) {
                int r = wm*32 + mt*16 + (lane >> 2);
                af[mt][0] = Ps[r*132     + kb + (lane & 3)];
                af[mt][1] = Ps[(r+8)*132 + kb + (lane & 3)];
                af[mt][2] = Ps[r*132     + kb + (lane & 3) + 4];
                af[mt][3] = Ps[(r+8)*132 + kb + (lane & 3) + 4];
            }
            #pragma unroll
            for (int nt = 0; nt < 4; nt++) {
                int d = wn*32 + nt*8 + (lane >> 2);
                uint32_t bf[2];
                bf[0] = Vs[d*132 + kb + (lane & 3)];
                bf[1] = Vs[d*132 + kb + (lane & 3) + 4];
                mma8(co[0][nt], af[0], bf);
                mma8(co[1][nt], af[1], bf);
            }
        }
    }

    /* ---- epilogue: combine row sums, write tf32 vals ---- */
    if ((lane & 3) == 0) {
        #pragma unroll
        for (int mt = 0; mt < 2; mt++)
            #pragma unroll
            for (int hf = 0; hf < 2; hf++)
                lsm[wn*128 + wm*32 + mt*16 + hf*8 + (lane >> 2)] = lrun[mt*2 + hf];
    }
    __syncthreads();
    #pragma unroll
    for (int mt = 0; mt < 2; mt++)
        #pragma unroll
        for (int hf = 0; hf < 2; hf++) {
            int row = wm*32 + mt*16 + hf*8 + (lane >> 2);
            float inv = 1.0f / (lsm[row] + lsm[128 + row]);
            #pragma unroll
            for (int nt = 0; nt < 4; nt++) {
                int col = wn*32 + nt*8 + (lane & 3)*2;
                uint2 v;
                v.x = f2tf(co[mt][nt][hf*2+0] * inv);
                v.y = f2tf(co[mt][nt][hf*2+1] * inv);
                *(uint2*)(g_valsu + ((size_t)b*Ss + qb*128 + row)*Ee + h*HDd + col) = v;
            }
        }
}

/* ===================================================================== */
extern "C" void kernel_launch(void* const* d_in, const int* in_sizes, int n_in,
                              void* d_out, int out_size)
{
    const float* x   = (const float*)d_in[0];
    const float* Wqk = (const float*)d_in[1];
    const float* bqk = (const float*)d_in[2];
    const float* Wv  = (const float*)d_in[3];
    const float* bv  = (const float*)d_in[4];
    const float* Wo  = (const float*)d_in[5];
    const float* bo  = (const float*)d_in[6];
    float* out = (float*)d_out;

    cudaFuncSetAttribute(attn_kernel, cudaFuncAttributeMaxDynamicSharedMemorySize, AT_SMEM);
    cudaFuncSetAttribute(tfgemm_p2,   cudaFuncAttributeMaxDynamicSharedMemorySize, TGP_SMEM);

    void *pMtu, *pXt, *pTu, *pWvT, *pWoT, *pVTu, *pValsu;
    cudaGetSymbolAddress(&pMtu,   g_Mtu);
    cudaGetSymbolAddress(&pXt,    g_xt);
    cudaGetSymbolAddress(&pTu,    g_tu);
    cudaGetSymbolAddress(&pWvT,   g_WvT);
    cudaGetSymbolAddress(&pWoT,   g_WoT);
    cudaGetSymbolAddress(&pVTu,   g_vTu);
    cudaGetSymbolAddress(&pValsu, g_valsu);

    /* 0. conversions */
    xcvt_kernel<<<BS*Ee/1024, 256>>>(x);
    wtrans_kernel<<<dim3(16, 16), dim3(32, 8)>>>(Wv, (uint32_t*)pWvT);
    wtrans_kernel<<<dim3(16, 16), dim3(32, 8)>>>(Wo, (uint32_t*)pWoT);

    /* 1. Mt[h] = SCALE * Wk . Wq^T  (tf32 out) */
    tfgemm_nt<<<dim3(4, 4, 8), 256>>>(
        Wqk + Ee, LDW, 2*Ee,
        Wqk,      LDW, 2*Ee,
        (uint32_t*)pMtu, Ee, (long)Ee*Ee, Ee, SCALE);

    rvec_kernel<<<16, 256>>>(Wqk, bqk);
    beta_kernel<<<8192, 256>>>(x);

    /* 2. t[h] = x @ M_h  (pipelined tf32) */
    tfgemm_p2<<<dim3(64, 4, 8), 256, TGP_SMEM>>>(
        (const uint32_t*)pXt, Ee, 0,
        (const uint32_t*)pMtu, Ee, (long)Ee*Ee,
        nullptr, nullptr,
        pTu, Ee, (long)BS*Ee, Ee, 0);

    /* 3. v^T[b][d][s] = Wv^T . x^T + bv (tensor path, direct to attn layout) */
    tfgemm_p2<<<dim3(4, 16, 4), 256, TGP_SMEM>>>(
        (const uint32_t*)pWvT, Ee, 0,
        (const uint32_t*)pXt, Ee, (long)Ss*Ee,
        bv, nullptr,
        pVTu, Ss, (long)Ee*Ss, Ee, 0);

    /* 4. fused attention (cross-kt pipelined mma.sync tf32) */
    attn_kernel<<<dim3(16, Hh, Bb), 256, AT_SMEM>>>();

    /* 5. out = vals @ Wo^T' + bo (tensor path, fp32 out) */
    tfgemm_p2<<<dim3(64, 4, 1), 256, TGP_SMEM>>>(
        (const uint32_t*)pValsu, Ee, 0,
        (const uint32_t*)pWoT, Ee, 0,
        nullptr, bo,
        out, Ee, 0, Ee, 0 + 1);
}

// round 12
// speedup vs baseline: 5.9087x; 1.0008x over previous
#include <cuda_runtime.h>
#include <math.h>
#include <stdint.h>

#define Bb   4
#define Ss   2048
#define Ee   512
#define Hh   8
#define HDd  64
#define BS   (Bb*Ss)            /* 8192 */
#define LDW  (2*Ee*Hh)          /* 8192 */
#define SCALE 0.044194173824159216f  /* 1/sqrt(512) */

/* ---- scratch (static device globals; no runtime allocation) ---- */
__device__ uint32_t g_Mtu  [(size_t)Hh*Ee*Ee];  /* tf32 Mt[h][c'][c] (8 MB)         */
__device__ float    g_r    [Hh*Ee];
__device__ float    g_beta [(size_t)Hh*BS];
__device__ uint32_t g_xt   [(size_t)BS*Ee];     /* tf32 x (17 MB)                   */
__device__ uint32_t g_tu   [(size_t)Hh*BS*Ee];  /* tf32 t[h][row][e'] (134 MB)      */
__device__ uint32_t g_WvT  [Ee*Ee];             /* tf32 Wv^T [d][c]                 */
__device__ uint32_t g_WoT  [Ee*Ee];             /* tf32 Wo^T [e][k]                 */
__device__ uint32_t g_vTu  [(size_t)BS*Ee];     /* tf32 v^T [(b*512+d)][s]          */
__device__ uint32_t g_valsu[(size_t)BS*Ee];     /* tf32 attention out (b,s,h*64+d)  */

/* =============================== helpers =============================== */
__device__ __forceinline__ uint32_t f2tf(float f){
    uint32_t r; asm("cvt.rna.tf32.f32 %0, %1;" : "=r"(r) : "f"(f)); return r;
}
__device__ __forceinline__ void mma8(float c[4], const uint32_t a[4], const uint32_t b[2]){
    asm volatile("mma.sync.aligned.m16n8k8.row.col.f32.tf32.tf32.f32 "
        "{%0,%1,%2,%3}, {%4,%5,%6,%7}, {%8,%9}, {%0,%1,%2,%3};"
        : "+f"(c[0]), "+f"(c[1]), "+f"(c[2]), "+f"(c[3])
        : "r"(a[0]), "r"(a[1]), "r"(a[2]), "r"(a[3]), "r"(b[0]), "r"(b[1]));
}
__device__ __forceinline__ uint32_t smem_u32(const void* p){
    uint32_t a;
    asm("{ .reg .u64 t; cvta.to.shared.u64 t, %1; cvt.u32.u64 %0, t; }" : "=r"(a) : "l"(p));
    return a;
}
__device__ __forceinline__ void cpa16(uint32_t dst, const void* src){
    asm volatile("cp.async.cg.shared.global [%0], [%1], 16;" :: "r"(dst), "l"(src) : "memory");
}
#define CP_COMMIT() asm volatile("cp.async.commit_group;" ::: "memory")
#define CP_WAIT0()  asm volatile("cp.async.wait_group 0;" ::: "memory")
#define CP_WAIT1()  asm volatile("cp.async.wait_group 1;" ::: "memory")
#define CP_WAIT2()  asm volatile("cp.async.wait_group 2;" ::: "memory")

/* x -> tf32 copy */
__global__ void xcvt_kernel(const float* __restrict__ x)
{
    size_t i = ((size_t)blockIdx.x * 256 + threadIdx.x) * 4;
    float4 v = *(const float4*)(x + i);
    uint4 o; o.x = f2tf(v.x); o.y = f2tf(v.y); o.z = f2tf(v.z); o.w = f2tf(v.w);
    *(uint4*)(g_xt + i) = o;
}

/* W[512x512] fp32 -> WT[n][k] tf32 */
__global__ void wtrans_kernel(const float* __restrict__ W, uint32_t* __restrict__ WT)
{
    __shared__ float ts[32][33];
    const int k0 = blockIdx.x * 32, n0 = blockIdx.y * 32;
    for (int i = threadIdx.y; i < 32; i += 8)
        ts[i][threadIdx.x] = W[(k0 + i) * Ee + n0 + threadIdx.x];
    __syncthreads();
    for (int i = threadIdx.y; i < 32; i += 8)
        WT[(n0 + i) * Ee + k0 + threadIdx.x] = f2tf(ts[threadIdx.x][i]);
}

/* =====================================================================
 * tf32 NT GEMM, fp32 inputs (cvt at STS), tf32 out. For M-precompute only.
 * ===================================================================== */
__global__ __launch_bounds__(256) void tfgemm_nt(
    const float* __restrict__ A, long lda, long sAz,
    const float* __restrict__ B, long ldb, long sBz,
    uint32_t* __restrict__ C, long ldc, long sCz,
    int Kdim, float alpha)
{
    __shared__ uint32_t As[128*36];
    __shared__ uint32_t Bs[128*36];
    const int tid = threadIdx.x;
    const int lane = tid & 31, wid = tid >> 5;
    const int wm = wid & 3, wn = wid >> 2;
    const int m0 = blockIdx.x*128, n0 = blockIdx.y*128, z = blockIdx.z;
    A += (size_t)z * sAz; B += (size_t)z * sBz; C += (size_t)z * sCz;

    float c[2][8][4];
    #pragma unroll
    for (int mt = 0; mt < 2; mt++)
        #pragma unroll
        for (int nt = 0; nt < 8; nt++)
            #pragma unroll
            for (int i = 0; i < 4; i++) c[mt][nt][i] = 0.f;

    float4 ra[4], rb[4];
    #pragma unroll
    for (int i = 0; i < 4; i++) {
        int s = tid + i*256, r = s >> 3, k4 = (s & 7) * 4;
        ra[i] = *(const float4*)(A + (size_t)(m0 + r)*lda + k4);
        rb[i] = *(const float4*)(B + (size_t)(n0 + r)*ldb + k4);
    }

    for (int kk = 0; kk < Kdim; kk += 32) {
        __syncthreads();
        #pragma unroll
        for (int i = 0; i < 4; i++) {
            int s = tid + i*256, r = s >> 3, k4 = (s & 7) * 4;
            uint32_t* pa = &As[r*36 + k4];
            pa[0]=f2tf(ra[i].x); pa[1]=f2tf(ra[i].y); pa[2]=f2tf(ra[i].z); pa[3]=f2tf(ra[i].w);
            uint32_t* pb = &Bs[r*36 + k4];
            pb[0]=f2tf(rb[i].x); pb[1]=f2tf(rb[i].y); pb[2]=f2tf(rb[i].z); pb[3]=f2tf(rb[i].w);
        }
        __syncthreads();
        if (kk + 32 < Kdim) {
            #pragma unroll
            for (int i = 0; i < 4; i++) {
                int s = tid + i*256, r = s >> 3, k4 = (s & 7) * 4;
                ra[i] = *(const float4*)(A + (size_t)(m0 + r)*lda + kk + 32 + k4);
                rb[i] = *(const float4*)(B + (size_t)(n0 + r)*ldb + kk + 32 + k4);
            }
        }
        #pragma unroll
        for (int kb = 0; kb < 32; kb += 8) {
            uint32_t af[2][4];
            #pragma unroll
            for (int mt = 0; mt < 2; mt++) {
                int r = wm*32 + mt*16 + (lane >> 2);
                af[mt][0] = As[r*36       + kb + (lane & 3)];
                af[mt][1] = As[(r+8)*36   + kb + (lane & 3)];
                af[mt][2] = As[r*36       + kb + (lane & 3) + 4];
                af[mt][3] = As[(r+8)*36   + kb + (lane & 3) + 4];
            }
            #pragma unroll
            for (int nt = 0; nt < 8; nt++) {
                int nr = wn*64 + nt*8 + (lane >> 2);
                uint32_t bf[2];
                bf[0] = Bs[nr*36 + kb + (lane & 3)];
                bf[1] = Bs[nr*36 + kb + (lane & 3) + 4];
                mma8(c[0][nt], af[0], bf);
                mma8(c[1][nt], af[1], bf);
            }
        }
    }

    #pragma unroll
    for (int mt = 0; mt < 2; mt++)
        #pragma unroll
        for (int nt = 0; nt < 8; nt++)
            #pragma unroll
            for (int hf = 0; hf < 2; hf++) {
                int row = m0 + wm*32 + mt*16 + hf*8 + (lane >> 2);
                int col = n0 + wn*64 + nt*8 + (lane & 3)*2;
                uint2 v;
                v.x = f2tf(alpha * c[mt][nt][hf*2+0]);
                v.y = f2tf(alpha * c[mt][nt][hf*2+1]);
                *(uint2*)(C + (size_t)row*ldc + col) = v;
            }
}

/* =====================================================================
 * Pipelined tf32 NT GEMM, tf32 in, cp.async 3-stage, 2 CTAs/SM.
 * Optional per-row bias (biasM), per-col bias (biasN), fp32 or tf32 out.
 * Serves: t-GEMM, v^T-GEMM, out-GEMM.
 * ===================================================================== */
#define TGP_SMEM (2*3*4608*4)   /* 110592 */
__global__ __launch_bounds__(256, 2) void tfgemm_p2(
    const uint32_t* __restrict__ A, long lda, long sAz,
    const uint32_t* __restrict__ B, long ldb, long sBz,
    const float* __restrict__ biasM, const float* __restrict__ biasN,
    void* __restrict__ Cv, long ldc, long sCz, int Kdim, int out_fp32)
{
    extern __shared__ uint32_t shp[];
    uint32_t* As = shp;
    uint32_t* Bs = shp + 3*4608;
    const uint32_t sA = smem_u32(As), sB = smem_u32(Bs);
    const int tid = threadIdx.x;
    const int lane = tid & 31, wid = tid >> 5;
    const int wm = wid & 3, wn = wid >> 2;
    const int m0 = blockIdx.x*128, n0 = blockIdx.y*128, z = blockIdx.z;
    A += (size_t)z * sAz; B += (size_t)z * sBz;

    float c[2][8][4];
    #pragma unroll
    for (int mt = 0; mt < 2; mt++)
        #pragma unroll
        for (int nt = 0; nt < 8; nt++)
            #pragma unroll
            for (int i = 0; i < 4; i++) c[mt][nt][i] = 0.f;

    const int nslab = Kdim / 32;
    #pragma unroll
    for (int st = 0; st < 2; st++) {
        int ec = st * 32;
        #pragma unroll
        for (int i = 0; i < 4; i++) {
            int s = tid + i*256, r = s >> 3, k4 = (s & 7) * 4;
            cpa16(sA + (uint32_t)(st*4608 + r*36 + k4)*4, A + (size_t)(m0 + r)*lda + ec + k4);
            cpa16(sB + (uint32_t)(st*4608 + r*36 + k4)*4, B + (size_t)(n0 + r)*ldb + ec + k4);
        }
        CP_COMMIT();
    }

    for (int j = 0; j < nslab; j++) {
        if (j < nslab - 1) { CP_WAIT1(); } else { CP_WAIT0(); }
        __syncthreads();
        const uint32_t* Aj = As + (j % 3) * 4608;
        const uint32_t* Bj = Bs + (j % 3) * 4608;
        #pragma unroll
        for (int kb = 0; kb < 32; kb += 8) {
            uint32_t af[2][4];
            #pragma unroll
            for (int mt = 0; mt < 2; mt++) {
                int r = wm*32 + mt*16 + (lane >> 2);
                af[mt][0] = Aj[r*36     + kb + (lane & 3)];
                af[mt][1] = Aj[(r+8)*36 + kb + (lane & 3)];
                af[mt][2] = Aj[r*36     + kb + (lane & 3) + 4];
                af[mt][3] = Aj[(r+8)*36 + kb + (lane & 3) + 4];
            }
            #pragma unroll
            for (int nt = 0; nt < 8; nt++) {
                int nr = wn*64 + nt*8 + (lane >> 2);
                uint32_t bf[2];
                bf[0] = Bj[nr*36 + kb + (lane & 3)];
                bf[1] = Bj[nr*36 + kb + (lane & 3) + 4];
                mma8(c[0][nt], af[0], bf);
                mma8(c[1][nt], af[1], bf);
            }
        }
        if (j + 2 < nslab) {
            int ec = (j + 2) * 32, bi = (j + 2) % 3;
            #pragma unroll
            for (int i = 0; i < 4; i++) {
                int s = tid + i*256, r = s >> 3, k4 = (s & 7) * 4;
                cpa16(sA + (uint32_t)(bi*4608 + r*36 + k4)*4, A + (size_t)(m0 + r)*lda + ec + k4);
                cpa16(sB + (uint32_t)(bi*4608 + r*36 + k4)*4, B + (size_t)(n0 + r)*ldb + ec + k4);
            }
            CP_COMMIT();
        }
    }

    #pragma unroll
    for (int mt = 0; mt < 2; mt++)
        #pragma unroll
        for (int nt = 0; nt < 8; nt++)
            #pragma unroll
            for (int hf = 0; hf < 2; hf++) {
                int row = m0 + wm*32 + mt*16 + hf*8 + (lane >> 2);
                int col = n0 + wn*64 + nt*8 + (lane & 3)*2;
                float bm = biasM ? biasM[row] : 0.f;
                float vx = c[mt][nt][hf*2+0] + bm;
                float vy = c[mt][nt][hf*2+1] + bm;
                if (biasN) { vx += biasN[col]; vy += biasN[col+1]; }
                size_t off = (size_t)z*sCz + (size_t)row*ldc + col;
                if (out_fp32) {
                    float2 o; o.x = vx; o.y = vy;
                    *(float2*)((float*)Cv + off) = o;
                } else {
                    uint2 o; o.x = f2tf(vx); o.y = f2tf(vy);
                    *(uint2*)((uint32_t*)Cv + off) = o;
                }
            }
}

__global__ void rvec_kernel(const float* __restrict__ Wqk, const float* __restrict__ bqk)
{
    int g = blockIdx.x * 256 + threadIdx.x;
    int h = g >> 9, cc = g & 511;
    const float* wk = Wqk + (long)cc * LDW + h * (2*Ee) + Ee;
    const float* bq = bqk + h * (2*Ee);
    float acc = 0.f;
    #pragma unroll 4
    for (int e = 0; e < Ee; e += 4)
        acc += wk[e]*bq[e] + wk[e+1]*bq[e+1] + wk[e+2]*bq[e+2] + wk[e+3]*bq[e+3];
    g_r[g] = acc * SCALE;
}

__global__ __launch_bounds__(256) void beta_kernel(const float* __restrict__ x)
{
    int w    = blockIdx.x * 8 + (threadIdx.x >> 5);
    int lane = threadIdx.x & 31;
    int h    = w >> 13;
    int row  = w & 8191;
    float acc = 0.f;
    #pragma unroll
    for (int i = 0; i < 4; i++) {
        int cc = lane * 4 + i * 128;
        float4 xv = *(const float4*)(x   + (long)row * Ee + cc);
        float4 rv = *(const float4*)(g_r + h * Ee + cc);
        acc += xv.x*rv.x + xv.y*rv.y + xv.z*rv.z + xv.w*rv.w;
    }
    #pragma unroll
    for (int off = 16; off; off >>= 1) acc += __shfl_xor_sync(0xffffffffu, acc, off);
    if (!lane) g_beta[w] = acc;
}

/* =====================================================================
 * Fused attention (mma.sync tf32, cp.async pipelined ACROSS key tiles).
 * CTA = (qb, h, b), 128 q-rows; 16 key tiles of 128; K=512 scores.
 * SMEM map (bytes): bsm 0 | lsm 512 | As 1536 (3x18432) | Bs 56832 (3x18432)
 *   | Ps 112128 (67584) | Vs 179712 (33792)  -> total 213504
 * ===================================================================== */
#define AT_SMEM 213504
__global__ __launch_bounds__(256, 1) void attn_kernel()
{
    extern __shared__ char sma[];
    float*    bsm = (float*)(sma);
    float*    lsm = (float*)(sma + 512);
    uint32_t* As  = (uint32_t*)(sma + 1536);
    uint32_t* Bs  = (uint32_t*)(sma + 56832);
    uint32_t* Ps  = (uint32_t*)(sma + 112128);
    uint32_t* Vs  = (uint32_t*)(sma + 179712);
    const uint32_t sA = smem_u32(As), sB = smem_u32(Bs), sV = smem_u32(Vs);

    const int tid = threadIdx.x, lane = tid & 31, wid = tid >> 5;
    const int wm = wid & 3, wn = wid >> 2;
    const int qb = blockIdx.x, h = blockIdx.y, b = blockIdx.z;

    const uint32_t* At = g_tu  + ((size_t)h*BS + (size_t)b*Ss + qb*128)*Ee;
    const uint32_t* Bx = g_xt  + ((size_t)b*Ss)*Ee;
    const uint32_t* Vt = g_vTu + ((size_t)b*Ee + h*HDd)*Ss;

    float co[2][4][4];
    #pragma unroll
    for (int mt = 0; mt < 2; mt++)
        #pragma unroll
        for (int nt = 0; nt < 4; nt++)
            #pragma unroll
            for (int i = 0; i < 4; i++) co[mt][nt][i] = 0.f;
    float lrun[4] = {0.f, 0.f, 0.f, 0.f};

    /* prologue: slabs 0,1 of kt=0 */
    #pragma unroll
    for (int st = 0; st < 2; st++) {
        int ec = st * 32;
        #pragma unroll
        for (int i = 0; i < 4; i++) {
            int s = tid + i*256, r = s >> 3, k4 = (s & 7) * 4;
            cpa16(sA + (uint32_t)(st*4608 + r*36 + k4)*4, At + (size_t)r*Ee + ec + k4);
            cpa16(sB + (uint32_t)(st*4608 + r*36 + k4)*4, Bx + (size_t)r*Ee + ec + k4);
        }
        CP_COMMIT();
    }

    for (int kt = 0; kt < 16; kt++) {
        __syncthreads();              /* PV(kt-1) done: Ps/Vs/bsm free */
        if (tid < 128)
            bsm[tid] = g_beta[(size_t)h*BS + (size_t)b*Ss + kt*128 + tid];

        /* V tile async — has the entire score phase to arrive */
        #pragma unroll
        for (int i = 0; i < 8; i++) {
            int s = tid + i*256, d = s >> 5, j4 = (s & 31) * 4;
            cpa16(sV + (uint32_t)(d*132 + j4)*4, Vt + (size_t)d*Ss + kt*128 + j4);
        }
        CP_COMMIT();

        float cs[2][8][4];
        #pragma unroll
        for (int mt = 0; mt < 2; mt++)
            #pragma unroll
            for (int nt = 0; nt < 8; nt++)
                #pragma unroll
                for (int i = 0; i < 4; i++) cs[mt][nt][i] = 0.f;

        const uint32_t* Bk = Bx + (size_t)kt*128*Ee;

        for (int j = 0; j < 16; j++) {
            if (j < 2) { CP_WAIT2(); } else { CP_WAIT1(); }
            __syncthreads();
            const uint32_t* Aj = As + (j % 3) * 4608;
            const uint32_t* Bj = Bs + (j % 3) * 4608;
            #pragma unroll
            for (int kb = 0; kb < 32; kb += 8) {
                uint32_t af[2][4];
                #pragma unroll
                for (int mt = 0; mt < 2; mt++) {
                    int r = wm*32 + mt*16 + (lane >> 2);
                    af[mt][0] = Aj[r*36     + kb + (lane & 3)];
                    af[mt][1] = Aj[(r+8)*36 + kb + (lane & 3)];
                    af[mt][2] = Aj[r*36     + kb + (lane & 3) + 4];
                    af[mt][3] = Aj[(r+8)*36 + kb + (lane & 3) + 4];
                }
                #pragma unroll
                for (int nt = 0; nt < 8; nt++) {
                    int nr = wn*64 + nt*8 + (lane >> 2);
                    uint32_t bf[2];
                    bf[0] = Bj[nr*36 + kb + (lane & 3)];
                    bf[1] = Bj[nr*36 + kb + (lane & 3) + 4];
                    mma8(cs[0][nt], af[0], bf);
                    mma8(cs[1][nt], af[1], bf);
                }
            }
            if (j < 14) {
                int ec = (j + 2) * 32, bi = (j + 2) % 3;
                #pragma unroll
                for (int i = 0; i < 4; i++) {
                    int s = tid + i*256, r = s >> 3, k4 = (s & 7) * 4;
                    cpa16(sA + (uint32_t)(bi*4608 + r*36 + k4)*4, At + (size_t)r*Ee + ec + k4);
                    cpa16(sB + (uint32_t)(bi*4608 + r*36 + k4)*4, Bk + (size_t)r*Ee + ec + k4);
                }
                CP_COMMIT();
            }
        }
        __syncthreads();              /* all warps done reading buf0/buf1 */

        /* keep the pipe full: prefetch slabs 0,1 of kt+1 during softmax+PV */
        if (kt < 15) {
            const uint32_t* Bk2 = Bx + (size_t)(kt+1)*128*Ee;
            #pragma unroll
            for (int st = 0; st < 2; st++) {
                int ec = st * 32;
                #pragma unroll
                for (int i = 0; i < 4; i++) {
                    int s = tid + i*256, r = s >> 3, k4 = (s & 7) * 4;
                    cpa16(sA + (uint32_t)(st*4608 + r*36 + k4)*4, At  + (size_t)r*Ee + ec + k4);
                    cpa16(sB + (uint32_t)(st*4608 + r*36 + k4)*4, Bk2 + (size_t)r*Ee + ec + k4);
                }
                CP_COMMIT();
            }
        }

        /* ---- unnormalized softmax; P -> SMEM (tf32) ---- */
        float part[4] = {0.f, 0.f, 0.f, 0.f};
        #pragma unroll
        for (int mt = 0; mt < 2; mt++)
            #pragma unroll
            for (int nt = 0; nt < 8; nt++) {
                int col = wn*64 + nt*8 + (lane & 3)*2;
                int r   = wm*32 + mt*16 + (lane >> 2);
                float p0 = __expf(cs[mt][nt][0] + bsm[col]);
                float p1 = __expf(cs[mt][nt][1] + bsm[col+1]);
                float p2 = __expf(cs[mt][nt][2] + bsm[col]);
                float p3 = __expf(cs[mt][nt][3] + bsm[col+1]);
                part[mt*2+0] += p0 + p1;
                part[mt*2+1] += p2 + p3;
                *(uint2*)&Ps[r*132 + col]     = make_uint2(f2tf(p0), f2tf(p1));
                *(uint2*)&Ps[(r+8)*132 + col] = make_uint2(f2tf(p2), f2tf(p3));
            }
        #pragma unroll
        for (int i = 0; i < 4; i++) {
            part[i] += __shfl_xor_sync(0xffffffffu, part[i], 1);
            part[i] += __shfl_xor_sync(0xffffffffu, part[i], 2);
            lrun[i] += part[i];
        }

        if (kt < 15) { CP_WAIT2(); } else { CP_WAIT0(); }   /* V done */
        __syncthreads();              /* V + Ps visible */

        /* ---- O += P @ V^T, K = 128 ---- */
        #pragma unroll
        for (int kb = 0; kb < 128; kb += 8) {
            uint32_t af[2][4];
            #pragma unroll
            for (int mt = 0; mt < 2; mt++) {
                int r = wm*32 + mt*16 + (lane >> 2);
                af[mt][0] = Ps[r*132     + kb + (lane & 3)];
                af[mt][1] = Ps[(r+8)*132 + kb + (lane & 3)];
                af[mt][2] = Ps[r*132     + kb + (lane & 3) + 4];
                af[mt][3] = Ps[(r+8)*132 + kb + (lane & 3) + 4];
            }
            #pragma unroll
            for (int nt = 0; nt < 4; nt++) {
                int d = wn*32 + nt*8 + (lane >> 2);
                uint32_t bf[2];
                bf[0] = Vs[d*132 + kb + (lane & 3)];
                bf[1] = Vs[d*132 + kb + (lane & 3) + 4];
                mma8(co[0][nt], af[0], bf);
                mma8(co[1][nt], af[1], bf);
            }
        }
    }

    /* ---- epilogue: combine row sums, write tf32 vals ---- */
    if ((lane & 3) == 0) {
        #pragma unroll
        for (int mt = 0; mt < 2; mt++)
            #pragma unroll
            for (int hf = 0; hf < 2; hf++)
                lsm[wn*128 + wm*32 + mt*16 + hf*8 + (lane >> 2)] = lrun[mt*2 + hf];
    }
    __syncthreads();
    #pragma unroll
    for (int mt = 0; mt < 2; mt++)
        #pragma unroll
        for (int hf = 0; hf < 2; hf++) {
            int row = wm*32 + mt*16 + hf*8 + (lane >> 2);
            float inv = 1.0f / (lsm[row] + lsm[128 + row]);
            #pragma unroll
            for (int nt = 0; nt < 4; nt++) {
                int col = wn*32 + nt*8 + (lane & 3)*2;
                uint2 v;
                v.x = f2tf(co[mt][nt][hf*2+0] * inv);
                v.y = f2tf(co[mt][nt][hf*2+1] * inv);
                *(uint2*)(g_valsu + ((size_t)b*Ss + qb*128 + row)*Ee + h*HDd + col) = v;
            }
        }
}

/* ===================================================================== */
extern "C" void kernel_launch(void* const* d_in, const int* in_sizes, int n_in,
                              void* d_out, int out_size)
{
    const float* x   = (const float*)d_in[0];
    const float* Wqk = (const float*)d_in[1];
    const float* bqk = (const float*)d_in[2];
    const float* Wv  = (const float*)d_in[3];
    const float* bv  = (const float*)d_in[4];
    const float* Wo  = (const float*)d_in[5];
    const float* bo  = (const float*)d_in[6];
    float* out = (float*)d_out;

    cudaFuncSetAttribute(attn_kernel, cudaFuncAttributeMaxDynamicSharedMemorySize, AT_SMEM);
    cudaFuncSetAttribute(tfgemm_p2,   cudaFuncAttributeMaxDynamicSharedMemorySize, TGP_SMEM);

    void *pMtu, *pXt, *pTu, *pWvT, *pWoT, *pVTu, *pValsu;
    cudaGetSymbolAddress(&pMtu,   g_Mtu);
    cudaGetSymbolAddress(&pXt,    g_xt);
    cudaGetSymbolAddress(&pTu,    g_tu);
    cudaGetSymbolAddress(&pWvT,   g_WvT);
    cudaGetSymbolAddress(&pWoT,   g_WoT);
    cudaGetSymbolAddress(&pVTu,   g_vTu);
    cudaGetSymbolAddress(&pValsu, g_valsu);

    /* 0. conversions */
    xcvt_kernel<<<BS*Ee/1024, 256>>>(x);
    wtrans_kernel<<<dim3(16, 16), dim3(32, 8)>>>(Wv, (uint32_t*)pWvT);
    wtrans_kernel<<<dim3(16, 16), dim3(32, 8)>>>(Wo, (uint32_t*)pWoT);

    /* 1. Mt[h] = SCALE * Wk . Wq^T  (tf32 out) */
    tfgemm_nt<<<dim3(4, 4, 8), 256>>>(
        Wqk + Ee, LDW, 2*Ee,
        Wqk,      LDW, 2*Ee,
        (uint32_t*)pMtu, Ee, (long)Ee*Ee, Ee, SCALE);

    rvec_kernel<<<16, 256>>>(Wqk, bqk);
    beta_kernel<<<8192, 256>>>(x);

    /* 2. t[h] = x @ M_h  (pipelined tf32) */
    tfgemm_p2<<<dim3(64, 4, 8), 256, TGP_SMEM>>>(
        (const uint32_t*)pXt, Ee, 0,
        (const uint32_t*)pMtu, Ee, (long)Ee*Ee,
        nullptr, nullptr,
        pTu, Ee, (long)BS*Ee, Ee, 0);

    /* 3. v^T[b][d][s] = Wv^T . x^T + bv (tensor path, direct to attn layout) */
    tfgemm_p2<<<dim3(4, 16, 4), 256, TGP_SMEM>>>(
        (const uint32_t*)pWvT, Ee, 0,
        (const uint32_t*)pXt, Ee, (long)Ss*Ee,
        bv, nullptr,
        pVTu, Ss, (long)Ee*Ss, Ee, 0);

    /* 4. fused attention (cross-kt pipelined mma.sync tf32) */
    attn_kernel<<<dim3(16, Hh, Bb), 256, AT_SMEM>>>();

    /* 5. out = vals @ Wo^T' + bo (tensor path, fp32 out) */
    tfgemm_p2<<<dim3(64, 4, 1), 256, TGP_SMEM>>>(
        (const uint32_t*)pValsu, Ee, 0,
        (const uint32_t*)pWoT, Ee, 0,
        nullptr, bo,
        out, Ee, 0, Ee, 0 + 1);
}

// round 13
// speedup vs baseline: 8.8467x; 1.4972x over previous
#include <cuda_runtime.h>
#include <cuda_fp16.h>
#include <math.h>
#include <stdint.h>

#define Bb   4
#define Ss   2048
#define Ee   512
#define Hh   8
#define HDd  64
#define BS   (Bb*Ss)
#define LDW  (2*Ee*Hh)
#define SCALE 0.044194173824159216f
#define INVMS 9.765625e-4f   /* 1/1024 */

__device__ __half g_Wqh [(size_t)Hh*Ee*Ee];
__device__ __half g_Wkh [(size_t)Hh*Ee*Ee];
__device__ __half g_Mth [(size_t)Hh*Ee*Ee];   /* 1024*SCALE*Wk.Wq^T */
__device__ __half g_xh  [(size_t)BS*Ee];
__device__ __half g_th  [(size_t)Hh*BS*Ee];   /* 1024*t */
__device__ __half g_WvTh[Ee*Ee];
__device__ __half g_vTh [(size_t)BS*Ee];      /* v^T [(b*512+d)][s] */
__device__ float  g_r   [Hh*Ee];
__device__ float  g_beta[(size_t)Hh*BS];
__device__ float  g_vals[(size_t)BS*Ee];

__device__ __forceinline__ void mma16(float c[4], uint32_t a0, uint32_t a1,
                                      uint32_t a2, uint32_t a3, uint32_t b0, uint32_t b1){
    asm volatile("mma.sync.aligned.m16n8k16.row.col.f32.f16.f16.f32 "
        "{%0,%1,%2,%3}, {%4,%5,%6,%7}, {%8,%9}, {%0,%1,%2,%3};"
        : "+f"(c[0]), "+f"(c[1]), "+f"(c[2]), "+f"(c[3])
        : "r"(a0), "r"(a1), "r"(a2), "r"(a3), "r"(b0), "r"(b1));
}
__device__ __forceinline__ uint32_t smem_u32(const void* p){
    uint32_t a;
    asm("{ .reg .u64 t; cvta.to.shared.u64 t, %1; cvt.u32.u64 %0, t; }" : "=r"(a) : "l"(p));
    return a;
}
__device__ __forceinline__ void cpa16(uint32_t dst, const void* src){
    asm volatile("cp.async.cg.shared.global [%0], [%1], 16;" :: "r"(dst), "l"(src) : "memory");
}
#define CP_COMMIT() asm volatile("cp.async.commit_group;" ::: "memory")
#define CP_WAIT(n)  asm volatile("cp.async.wait_group %0;" :: "n"(n) : "memory")
__device__ __forceinline__ uint32_t packh2(float lo, float hi){
    __half2 h = __floats2half2_rn(lo, hi);
    return *(uint32_t*)&h;
}

__global__ void xcvt_kernel(const float* __restrict__ x){
    size_t i = ((size_t)blockIdx.x * 256 + threadIdx.x) * 8;
    float4 v0 = *(const float4*)(x + i), v1 = *(const float4*)(x + i + 4);
    uint4 o;
    o.x = packh2(v0.x, v0.y); o.y = packh2(v0.z, v0.w);
    o.z = packh2(v1.x, v1.y); o.w = packh2(v1.z, v1.w);
    *(uint4*)(g_xh + i) = o;
}

__global__ void qkcvt_kernel(const float* __restrict__ Wqk){
    int g = blockIdx.x * 256 + threadIdx.x;
    int h = g >> 15, rem = g & 32767;
    int c = rem >> 6, e8 = (rem & 63) * 8;
    const float* q = Wqk + (size_t)c * LDW + h * (2*Ee) + e8;
    float4 q0 = *(const float4*)(q), q1 = *(const float4*)(q + 4);
    float4 k0 = *(const float4*)(q + Ee), k1 = *(const float4*)(q + Ee + 4);
    size_t o = ((size_t)h*Ee + c)*Ee + e8;
    uint4 uq, uk;
    uq.x = packh2(q0.x,q0.y); uq.y = packh2(q0.z,q0.w);
    uq.z = packh2(q1.x,q1.y); uq.w = packh2(q1.z,q1.w);
    uk.x = packh2(k0.x,k0.y); uk.y = packh2(k0.z,k0.w);
    uk.z = packh2(k1.x,k1.y); uk.w = packh2(k1.z,k1.w);
    *(uint4*)(g_Wqh + o) = uq;
    *(uint4*)(g_Wkh + o) = uk;
}

__global__ void wtrans_kernel(const float* __restrict__ W){
    __shared__ float ts[32][33];
    const int k0 = blockIdx.x * 32, n0 = blockIdx.y * 32;
    for (int i = threadIdx.y; i < 32; i += 8)
        ts[i][threadIdx.x] = W[(k0 + i) * Ee + n0 + threadIdx.x];
    __syncthreads();
    for (int i = threadIdx.y; i < 32; i += 8)
        g_WvTh[(n0 + i) * Ee + k0 + threadIdx.x] = __float2half_rn(ts[threadIdx.x][i]);
}

/* pipelined fp16 NT GEMM: C[z][m][n] = alpha*sum_k A[m][k]B[n][k] (+biasM[m]) */
#define HG_SMEM 40960
__global__ __launch_bounds__(256, 2) void hgemm_p(
    const __half* __restrict__ A, long lda, long sAz,
    const __half* __restrict__ B, long ldb, long sBz,
    const float* __restrict__ biasM,
    __half* __restrict__ C, long ldc, long sCz, int Kdim, float alpha)
{
    extern __shared__ __half shh[];
    __half* As = shh;                  /* 2 x 128x40 */
    __half* Bs = shh + 2*128*40;
    const uint32_t sA = smem_u32(As), sB = smem_u32(Bs);
    const int tid = threadIdx.x, lane = tid & 31, wid = tid >> 5;
    const int wm = wid & 3, wn = wid >> 2;
    const int m0 = blockIdx.x*128, n0 = blockIdx.y*128, z = blockIdx.z;
    A += (size_t)z * sAz; B += (size_t)z * sBz;

    float c[2][8][4];
    #pragma unroll
    for (int mt = 0; mt < 2; mt++)
        #pragma unroll
        for (int nt = 0; nt < 8; nt++)
            #pragma unroll
            for (int i = 0; i < 4; i++) c[mt][nt][i] = 0.f;

    const int nslab = Kdim / 32;
    #pragma unroll
    for (int i = 0; i < 2; i++) {
        int s = tid + i*256, r = s >> 2, q8 = (s & 3) * 8;
        cpa16(sA + (uint32_t)(r*40 + q8)*2, A + (size_t)(m0 + r)*lda + q8);
        cpa16(sB + (uint32_t)(r*40 + q8)*2, B + (size_t)(n0 + r)*ldb + q8);
    }
    CP_COMMIT();

    for (int j = 0; j < nslab; j++) {
        CP_WAIT(0);
        __syncthreads();
        if (j + 1 < nslab) {
            int ec = (j + 1) * 32;
            uint32_t bo = ((j + 1) & 1) ? (uint32_t)(128*40*2) : 0u;
            #pragma unroll
            for (int i = 0; i < 2; i++) {
                int s = tid + i*256, r = s >> 2, q8 = (s & 3) * 8;
                cpa16(sA + bo + (uint32_t)(r*40 + q8)*2, A + (size_t)(m0 + r)*lda + ec + q8);
                cpa16(sB + bo + (uint32_t)(r*40 + q8)*2, B + (size_t)(n0 + r)*ldb + ec + q8);
            }
            CP_COMMIT();
        }
        const __half* Aj = As + (j & 1) * (128*40);
        const __half* Bj = Bs + (j & 1) * (128*40);
        #pragma unroll
        for (int kc = 0; kc < 2; kc++) {
            int kb = kc*16 + 2*(lane & 3);
            uint32_t af[2][4];
            #pragma unroll
            for (int mt = 0; mt < 2; mt++) {
                int r = wm*32 + mt*16 + (lane >> 2);
                af[mt][0] = *(const uint32_t*)(Aj + r*40 + kb);
                af[mt][1] = *(const uint32_t*)(Aj + (r+8)*40 + kb);
                af[mt][2] = *(const uint32_t*)(Aj + r*40 + kb + 8);
                af[mt][3] = *(const uint32_t*)(Aj + (r+8)*40 + kb + 8);
            }
            #pragma unroll
            for (int nt = 0; nt < 8; nt++) {
                int col = wn*64 + nt*8 + (lane >> 2);
                uint32_t b0 = *(const uint32_t*)(Bj + col*40 + kb);
                uint32_t b1 = *(const uint32_t*)(Bj + col*40 + kb + 8);
                mma16(c[0][nt], af[0][0], af[0][1], af[0][2], af[0][3], b0, b1);
                mma16(c[1][nt], af[1][0], af[1][1], af[1][2], af[1][3], b0, b1);
            }
        }
    }

    #pragma unroll
    for (int mt = 0; mt < 2; mt++)
        #pragma unroll
        for (int nt = 0; nt < 8; nt++)
            #pragma unroll
            for (int hf = 0; hf < 2; hf++) {
                int row = m0 + wm*32 + mt*16 + hf*8 + (lane >> 2);
                int col = n0 + wn*64 + nt*8 + (lane & 3)*2;
                float bm = biasM ? biasM[row] : 0.f;
                *(uint32_t*)(C + (size_t)z*sCz + (size_t)row*ldc + col) =
                    packh2(alpha*c[mt][nt][hf*2+0] + bm, alpha*c[mt][nt][hf*2+1] + bm);
            }
}

__global__ void rvec_kernel(const float* __restrict__ Wqk, const float* __restrict__ bqk){
    int g = blockIdx.x * 256 + threadIdx.x;
    int h = g >> 9, cc = g & 511;
    const float* wk = Wqk + (long)cc * LDW + h * (2*Ee) + Ee;
    const float* bq = bqk + h * (2*Ee);
    float acc = 0.f;
    #pragma unroll 4
    for (int e = 0; e < Ee; e += 4)
        acc += wk[e]*bq[e] + wk[e+1]*bq[e+1] + wk[e+2]*bq[e+2] + wk[e+3]*bq[e+3];
    g_r[g] = acc * SCALE;
}

__global__ __launch_bounds__(256) void beta_kernel(const float* __restrict__ x){
    int w = blockIdx.x * 8 + (threadIdx.x >> 5);
    int lane = threadIdx.x & 31;
    int h = w >> 13, row = w & 8191;
    float acc = 0.f;
    #pragma unroll
    for (int i = 0; i < 4; i++) {
        int cc = lane * 4 + i * 128;
        float4 xv = *(const float4*)(x + (long)row * Ee + cc);
        float4 rv = *(const float4*)(g_r + h * Ee + cc);
        acc += xv.x*rv.x + xv.y*rv.y + xv.z*rv.z + xv.w*rv.w;
    }
    #pragma unroll
    for (int off = 16; off; off >>= 1) acc += __shfl_xor_sync(0xffffffffu, acc, off);
    if (!lane) g_beta[w] = acc;
}

/* fp32 SGEMM for the final out projection (error-critical) */
__global__ __launch_bounds__(256) void sgemm_kernel(
    const float* __restrict__ A, const float* __restrict__ Bm,
    const float* __restrict__ bias, float* __restrict__ C, int Ndim, int Kdim)
{
    const int m0 = blockIdx.x * 128, n0 = blockIdx.y * 128;
    const int tid = threadIdx.x, tx = tid & 15, ty = tid >> 4;
    __shared__ float As[16][132];
    __shared__ float Bs[16][128];
    float acc[8][8];
    #pragma unroll
    for (int i = 0; i < 8; i++)
        #pragma unroll
        for (int j = 0; j < 8; j++) acc[i][j] = 0.f;
    for (int kk = 0; kk < Kdim; kk += 16) {
        #pragma unroll
        for (int i = 0; i < 2; i++) {
            int slot = tid + (i << 8);
            int m = slot >> 2, k4 = (slot & 3) << 2;
            float4 av = *(const float4*)(A + (long)(m0 + m) * Kdim + kk + k4);
            As[k4+0][m] = av.x; As[k4+1][m] = av.y; As[k4+2][m] = av.z; As[k4+3][m] = av.w;
            int r = slot >> 5, c4 = (slot & 31) << 2;
            *(float4*)&Bs[r][c4] = *(const float4*)(Bm + (long)(kk + r) * Ndim + n0 + c4);
        }
        __syncthreads();
        #pragma unroll
        for (int k = 0; k < 16; k++) {
            float a[8], b[8];
            *(float4*)(a)     = *(const float4*)&As[k][ty*4];
            *(float4*)(a + 4) = *(const float4*)&As[k][ty*4 + 64];
            *(float4*)(b)     = *(const float4*)&Bs[k][tx*4];
            *(float4*)(b + 4) = *(const float4*)&Bs[k][tx*4 + 64];
            #pragma unroll
            for (int i = 0; i < 8; i++)
                #pragma unroll
                for (int j = 0; j < 8; j++) acc[i][j] += a[i] * b[j];
        }
        __syncthreads();
    }
    float b0[8];
    *(float4*)(b0)     = *(const float4*)(bias + n0 + tx*4);
    *(float4*)(b0 + 4) = *(const float4*)(bias + n0 + 64 + tx*4);
    #pragma unroll
    for (int rh = 0; rh < 2; rh++)
        #pragma unroll
        for (int i = 0; i < 4; i++) {
            int row = m0 + rh*64 + ty*4 + i;
            #pragma unroll
            for (int ch = 0; ch < 2; ch++)
                *(float4*)(C + (long)row * Ndim + n0 + ch*64 + tx*4) =
                    make_float4(acc[rh*4+i][ch*4+0] + b0[ch*4+0], acc[rh*4+i][ch*4+1] + b0[ch*4+1],
                                acc[rh*4+i][ch*4+2] + b0[ch*4+2], acc[rh*4+i][ch*4+3] + b0[ch*4+3]);
        }
}

/* =====================================================================
 * Fused attention, fp16 mma, register-resident P (FA2 repack).
 * SMEM: bsm 0(512) lsm 512(1024) As 1536(3x10240) Bs 32256(3x10240)
 *       Vs 62976(17408) = 80384; Osm reuses As/Bs (33792B).
 * ===================================================================== */
#define AT_SMEM 80384
__global__ __launch_bounds__(256, 1) void attn_kernel(){
    extern __shared__ char sma[];
    float*  bsm = (float*)(sma);
    float*  lsm = (float*)(sma + 512);
    __half* As  = (__half*)(sma + 1536);
    __half* Bs  = (__half*)(sma + 32256);
    __half* Vs  = (__half*)(sma + 62976);
    float*  Osm = (float*)(sma + 1536);
    const uint32_t sA = smem_u32(As), sB = smem_u32(Bs), sV = smem_u32(Vs);

    const int tid = threadIdx.x, lane = tid & 31, wid = tid >> 5;
    const int wm = wid & 3, wn = wid >> 2;
    const int qb = blockIdx.x, h = blockIdx.y, b = blockIdx.z;
    const int g = lane >> 2, tg2 = 2*(lane & 3);

    const __half* At = g_th  + ((size_t)h*BS + (size_t)b*Ss + qb*128)*Ee;
    const __half* Bx = g_xh  + ((size_t)b*Ss)*Ee;
    const __half* Vt = g_vTh + ((size_t)b*Ee + h*HDd)*Ss;

    float co[2][8][4];
    #pragma unroll
    for (int mt = 0; mt < 2; mt++)
        #pragma unroll
        for (int nt = 0; nt < 8; nt++)
            #pragma unroll
            for (int i = 0; i < 4; i++) co[mt][nt][i] = 0.f;
    float lrun[4] = {0.f, 0.f, 0.f, 0.f};

    /* prologue: slabs 0,1 of kt=0 */
    #pragma unroll
    for (int st = 0; st < 2; st++) {
        #pragma unroll
        for (int i = 0; i < 2; i++) {
            int s = tid + i*256, r = s >> 2, q8 = (s & 3) * 8;
            cpa16(sA + (uint32_t)(st*5120 + r*40 + q8)*2, At + (size_t)r*Ee + st*32 + q8);
            cpa16(sB + (uint32_t)(st*5120 + r*40 + q8)*2, Bx + (size_t)r*Ee + st*32 + q8);
        }
        CP_COMMIT();
    }

    for (int kt = 0; kt < 16; kt++) {
        __syncthreads();                       /* PV(kt-1) done with Vs/bsm */
        if (tid < 128)
            bsm[tid] = g_beta[(size_t)h*BS + (size_t)b*Ss + kt*128 + tid];
        #pragma unroll
        for (int i = 0; i < 4; i++) {          /* V group */
            int s = tid + i*256, d = s >> 4, j8 = (s & 15) * 8;
            cpa16(sV + (uint32_t)(d*136 + j8)*2, Vt + (size_t)d*Ss + kt*128 + j8);
        }
        CP_COMMIT();

        float cs[2][8][4];
        #pragma unroll
        for (int mt = 0; mt < 2; mt++)
            #pragma unroll
            for (int nt = 0; nt < 8; nt++)
                #pragma unroll
                for (int i = 0; i < 4; i++) cs[mt][nt][i] = 0.f;

        const __half* Bk = Bx + (size_t)kt*128*Ee;

        for (int j = 0; j < 16; j++) {
            if (j < 14) {
                int ec = (j + 2) * 32;
                uint32_t bo = (uint32_t)(((j + 2) % 3) * 10240);
                #pragma unroll
                for (int i = 0; i < 2; i++) {
                    int s = tid + i*256, r = s >> 2, q8 = (s & 3) * 8;
                    cpa16(sA + bo + (uint32_t)(r*40 + q8)*2, At + (size_t)r*Ee + ec + q8);
                    cpa16(sB + bo + (uint32_t)(r*40 + q8)*2, Bk + (size_t)r*Ee + ec + q8);
                }
                CP_COMMIT();
            }
            if (j <= 1)       { CP_WAIT(3); }
            else if (j <= 13) { CP_WAIT(2); }
            else if (j == 14) { CP_WAIT(1); }
            else              { CP_WAIT(0); }
            __syncthreads();
            const __half* Aj = As + (j % 3) * 5120;
            const __half* Bj = Bs + (j % 3) * 5120;
            #pragma unroll
            for (int kc = 0; kc < 2; kc++) {
                int kb = kc*16 + tg2;
                uint32_t af[2][4];
                #pragma unroll
                for (int mt = 0; mt < 2; mt++) {
                    int r = wm*32 + mt*16 + g;
                    af[mt][0] = *(const uint32_t*)(Aj + r*40 + kb);
                    af[mt][1] = *(const uint32_t*)(Aj + (r+8)*40 + kb);
                    af[mt][2] = *(const uint32_t*)(Aj + r*40 + kb + 8);
                    af[mt][3] = *(const uint32_t*)(Aj + (r+8)*40 + kb + 8);
                }
                #pragma unroll
                for (int nt = 0; nt < 8; nt++) {
                    int col = wn*64 + nt*8 + g;
                    uint32_t b0 = *(const uint32_t*)(Bj + col*40 + kb);
                    uint32_t b1 = *(const uint32_t*)(Bj + col*40 + kb + 8);
                    mma16(cs[0][nt], af[0][0], af[0][1], af[0][2], af[0][3], b0, b1);
                    mma16(cs[1][nt], af[1][0], af[1][1], af[1][2], af[1][3], b0, b1);
                }
            }
        }
        __syncthreads();                 /* all warps done with As/Bs + V visible */

        if (kt < 15) {                   /* keep pipe full through softmax+PV */
            const __half* Bk2 = Bx + (size_t)(kt+1)*128*Ee;
            #pragma unroll
            for (int st = 0; st < 2; st++) {
                #pragma unroll
                for (int i = 0; i < 2; i++) {
                    int s = tid + i*256, r = s >> 2, q8 = (s & 3) * 8;
                    cpa16(sA + (uint32_t)(st*5120 + r*40 + q8)*2, At  + (size_t)r*Ee + st*32 + q8);
                    cpa16(sB + (uint32_t)(st*5120 + r*40 + q8)*2, Bk2 + (size_t)r*Ee + st*32 + q8);
                }
                CP_COMMIT();
            }
        }

        /* softmax in registers: p = exp(s/1024 + beta); pack to fp16 A-frags */
        uint32_t pA[2][8], pB[2][8];
        float part[4] = {0.f, 0.f, 0.f, 0.f};
        #pragma unroll
        for (int mt = 0; mt < 2; mt++)
            #pragma unroll
            for (int nt = 0; nt < 8; nt++) {
                int col = wn*64 + nt*8 + tg2;
                float p0 = __expf(fmaf(cs[mt][nt][0], INVMS, bsm[col]));
                float p1 = __expf(fmaf(cs[mt][nt][1], INVMS, bsm[col+1]));
                float p2 = __expf(fmaf(cs[mt][nt][2], INVMS, bsm[col]));
                float p3 = __expf(fmaf(cs[mt][nt][3], INVMS, bsm[col+1]));
                part[mt*2+0] += p0 + p1;
                part[mt*2+1] += p2 + p3;
                pA[mt][nt] = packh2(p0, p1);
                pB[mt][nt] = packh2(p2, p3);
            }
        #pragma unroll
        for (int i = 0; i < 4; i++) {
            part[i] += __shfl_xor_sync(0xffffffffu, part[i], 1);
            part[i] += __shfl_xor_sync(0xffffffffu, part[i], 2);
            lrun[i] += part[i];
        }

        /* O += P @ V^T over this warp's 64-key half (4 chunks of k16) */
        #pragma unroll
        for (int mt = 0; mt < 2; mt++)
            #pragma unroll
            for (int kc = 0; kc < 4; kc++) {
                uint32_t a0 = pA[mt][2*kc], a1 = pB[mt][2*kc];
                uint32_t a2 = pA[mt][2*kc+1], a3 = pB[mt][2*kc+1];
                int kb = wn*64 + kc*16 + tg2;
                #pragma unroll
                for (int nt = 0; nt < 8; nt++) {
                    int d = nt*8 + g;
                    uint32_t b0 = *(const uint32_t*)(Vs + d*136 + kb);
                    uint32_t b1 = *(const uint32_t*)(Vs + d*136 + kb + 8);
                    mma16(co[mt][nt], a0, a1, a2, a3, b0, b1);
                }
            }
    }

    /* epilogue: combine the two warp-column partials via smem */
    if ((lane & 3) == 0) {
        #pragma unroll
        for (int mt = 0; mt < 2; mt++)
            #pragma unroll
            for (int hf = 0; hf < 2; hf++)
                lsm[wn*128 + wm*32 + mt*16 + hf*8 + g] = lrun[mt*2 + hf];
    }
    __syncthreads();
    if (wn == 0) {
        #pragma unroll
        for (int mt = 0; mt < 2; mt++)
            #pragma unroll
            for (int nt = 0; nt < 8; nt++)
                #pragma unroll
                for (int hf = 0; hf < 2; hf++) {
                    int row = wm*32 + mt*16 + hf*8 + g;
                    *(float2*)&Osm[row*66 + nt*8 + tg2] =
                        make_float2(co[mt][nt][hf*2+0], co[mt][nt][hf*2+1]);
                }
    }
    __syncthreads();
    if (wn == 1) {
        #pragma unroll
        for (int mt = 0; mt < 2; mt++)
            #pragma unroll
            for (int hf = 0; hf < 2; hf++) {
                int row = wm*32 + mt*16 + hf*8 + g;
                float inv = 1.0f / (lsm[row] + lsm[128 + row]);
                #pragma unroll
                for (int nt = 0; nt < 8; nt++) {
                    float2 o = *(float2*)&Osm[row*66 + nt*8 + tg2];
                    o.x = (o.x + co[mt][nt][hf*2+0]) * inv;
                    o.y = (o.y + co[mt][nt][hf*2+1]) * inv;
                    *(float2*)(g_vals + ((size_t)b*Ss + qb*128 + row)*Ee + h*HDd + nt*8 + tg2) = o;
                }
            }
    }
}

extern "C" void kernel_launch(void* const* d_in, const int* in_sizes, int n_in,
                              void* d_out, int out_size)
{
    const float* x   = (const float*)d_in[0];
    const float* Wqk = (const float*)d_in[1];
    const float* bqk = (const float*)d_in[2];
    const float* Wv  = (const float*)d_in[3];
    const float* bv  = (const float*)d_in[4];
    const float* Wo  = (const float*)d_in[5];
    const float* bo  = (const float*)d_in[6];
    float* out = (float*)d_out;

    cudaFuncSetAttribute(attn_kernel, cudaFuncAttributeMaxDynamicSharedMemorySize, AT_SMEM);
    cudaFuncSetAttribute(hgemm_p,     cudaFuncAttributeMaxDynamicSharedMemorySize, HG_SMEM);

    void *pWq, *pWk, *pMt, *pXh, *pTh, *pWvT, *pVT, *pVals;
    cudaGetSymbolAddress(&pWq,  g_Wqh);
    cudaGetSymbolAddress(&pWk,  g_Wkh);
    cudaGetSymbolAddress(&pMt,  g_Mth);
    cudaGetSymbolAddress(&pXh,  g_xh);
    cudaGetSymbolAddress(&pTh,  g_th);
    cudaGetSymbolAddress(&pWvT, g_WvTh);
    cudaGetSymbolAddress(&pVT,  g_vTh);
    cudaGetSymbolAddress(&pVals, g_vals);

    xcvt_kernel<<<BS*Ee/2048, 256>>>(x);
    qkcvt_kernel<<<1024, 256>>>(Wqk);
    wtrans_kernel<<<dim3(16, 16), dim3(32, 8)>>>(Wv);
    rvec_kernel<<<16, 256>>>(Wqk, bqk);
    beta_kernel<<<8192, 256>>>(x);

    /* Mt[h] = 1024*SCALE * Wk . Wq^T */
    hgemm_p<<<dim3(4, 4, 8), 256, HG_SMEM>>>(
        (const __half*)pWk, Ee, (long)Ee*Ee,
        (const __half*)pWq, Ee, (long)Ee*Ee,
        nullptr, (__half*)pMt, Ee, (long)Ee*Ee, Ee, SCALE * 1024.0f);

    /* t*1024 = x @ Mt^T */
    hgemm_p<<<dim3(64, 4, 8), 256, HG_SMEM>>>(
        (const __half*)pXh, Ee, 0,
        (const __half*)pMt, Ee, (long)Ee*Ee,
        nullptr, (__half*)pTh, Ee, (long)BS*Ee, Ee, 1.0f);

    /* v^T[b][d][s] = Wv^T . x^T + bv */
    hgemm_p<<<dim3(4, 16, 4), 256, HG_SMEM>>>(
        (const __half*)pWvT, Ee, 0,
        (const __half*)pXh, Ee, (long)Ss*Ee,
        bv, (__half*)pVT, Ss, (long)Ee*Ss, Ee, 1.0f);

    attn_kernel<<<dim3(16, Hh, Bb), 256, AT_SMEM>>>();

    /* out = vals @ Wo + bo  (fp32, error-critical) */
    sgemm_kernel<<<dim3(64, 4), 256>>>((const float*)pVals, Wo, bo, out, Ee, Ee);
}

// round 16
// speedup vs baseline: 10.3621x; 1.1713x over previous
#include <cuda_runtime.h>
#include <cuda_fp16.h>
#include <math.h>
#include <stdint.h>

#define Bb   4
#define Ss   2048
#define Ee   512
#define Hh   8
#define HDd  64
#define BS   (Bb*Ss)
#define LDW  (2*Ee*Hh)
#define SCALE 0.044194173824159216f
#define INVMS 9.765625e-4f   /* 1/1024 */

__device__ __half g_Wqh [(size_t)Hh*Ee*Ee];
__device__ __half g_Wkh [(size_t)Hh*Ee*Ee];
__device__ __half g_Mth [(size_t)Hh*Ee*Ee];   /* 1024*SCALE*Wk.Wq^T */
__device__ __half g_xh  [(size_t)BS*Ee];
__device__ __half g_th  [(size_t)Hh*BS*Ee];   /* 1024*t */
__device__ __half g_WvTh[Ee*Ee];
__device__ __half g_vTh [(size_t)BS*Ee];      /* v^T [(b*512+d)][s] */
__device__ float  g_r   [Hh*Ee];
__device__ float  g_beta[(size_t)Hh*BS];
__device__ float  g_vals[(size_t)BS*Ee];

__device__ __forceinline__ void mma16(float c[4], uint32_t a0, uint32_t a1,
                                      uint32_t a2, uint32_t a3, uint32_t b0, uint32_t b1){
    asm volatile("mma.sync.aligned.m16n8k16.row.col.f32.f16.f16.f32 "
        "{%0,%1,%2,%3}, {%4,%5,%6,%7}, {%8,%9}, {%0,%1,%2,%3};"
        : "+f"(c[0]), "+f"(c[1]), "+f"(c[2]), "+f"(c[3])
        : "r"(a0), "r"(a1), "r"(a2), "r"(a3), "r"(b0), "r"(b1));
}
__device__ __forceinline__ uint32_t smem_u32(const void* p){
    uint32_t a;
    asm("{ .reg .u64 t; cvta.to.shared.u64 t, %1; cvt.u32.u64 %0, t; }" : "=r"(a) : "l"(p));
    return a;
}
__device__ __forceinline__ void cpa16(uint32_t dst, const void* src){
    asm volatile("cp.async.cg.shared.global [%0], [%1], 16;" :: "r"(dst), "l"(src) : "memory");
}
#define CP_COMMIT() asm volatile("cp.async.commit_group;" ::: "memory")
#define CP_WAIT(n)  asm volatile("cp.async.wait_group %0;" :: "n"(n) : "memory")
__device__ __forceinline__ uint32_t packh2(float lo, float hi){
    __half2 h = __floats2half2_rn(lo, hi);
    return *(uint32_t*)&h;
}

__global__ void xcvt_kernel(const float* __restrict__ x){
    size_t i = ((size_t)blockIdx.x * 256 + threadIdx.x) * 8;
    float4 v0 = *(const float4*)(x + i), v1 = *(const float4*)(x + i + 4);
    uint4 o;
    o.x = packh2(v0.x, v0.y); o.y = packh2(v0.z, v0.w);
    o.z = packh2(v1.x, v1.y); o.w = packh2(v1.z, v1.w);
    *(uint4*)(g_xh + i) = o;
}

__global__ void qkcvt_kernel(const float* __restrict__ Wqk){
    int g = blockIdx.x * 256 + threadIdx.x;
    int h = g >> 15, rem = g & 32767;
    int c = rem >> 6, e8 = (rem & 63) * 8;
    const float* q = Wqk + (size_t)c * LDW + h * (2*Ee) + e8;
    float4 q0 = *(const float4*)(q), q1 = *(const float4*)(q + 4);
    float4 k0 = *(const float4*)(q + Ee), k1 = *(const float4*)(q + Ee + 4);
    size_t o = ((size_t)h*Ee + c)*Ee + e8;
    uint4 uq, uk;
    uq.x = packh2(q0.x,q0.y); uq.y = packh2(q0.z,q0.w);
    uq.z = packh2(q1.x,q1.y); uq.w = packh2(q1.z,q1.w);
    uk.x = packh2(k0.x,k0.y); uk.y = packh2(k0.z,k0.w);
    uk.z = packh2(k1.x,k1.y); uk.w = packh2(k1.z,k1.w);
    *(uint4*)(g_Wqh + o) = uq;
    *(uint4*)(g_Wkh + o) = uk;
}

__global__ void wtrans_kernel(const float* __restrict__ W){
    __shared__ float ts[32][33];
    const int k0 = blockIdx.x * 32, n0 = blockIdx.y * 32;
    for (int i = threadIdx.y; i < 32; i += 8)
        ts[i][threadIdx.x] = W[(k0 + i) * Ee + n0 + threadIdx.x];
    __syncthreads();
    for (int i = threadIdx.y; i < 32; i += 8)
        g_WvTh[(n0 + i) * Ee + k0 + threadIdx.x] = __float2half_rn(ts[threadIdx.x][i]);
}

/* pipelined fp16 NT GEMM: C[z][m][n] = alpha*sum_k A[m][k]B[n][k] (+biasM[m]) */
#define HG_SMEM 40960
__global__ __launch_bounds__(256, 2) void hgemm_p(
    const __half* __restrict__ A, long lda, long sAz,
    const __half* __restrict__ B, long ldb, long sBz,
    const float* __restrict__ biasM,
    __half* __restrict__ C, long ldc, long sCz, int Kdim, float alpha)
{
    extern __shared__ __half shh[];
    __half* As = shh;                  /* 2 x 128x40 */
    __half* Bs = shh + 2*128*40;
    const uint32_t sA = smem_u32(As), sB = smem_u32(Bs);
    const int tid = threadIdx.x, lane = tid & 31, wid = tid >> 5;
    const int wm = wid & 3, wn = wid >> 2;
    const int m0 = blockIdx.x*128, n0 = blockIdx.y*128, z = blockIdx.z;
    A += (size_t)z * sAz; B += (size_t)z * sBz;

    float c[2][8][4];
    #pragma unroll
    for (int mt = 0; mt < 2; mt++)
        #pragma unroll
        for (int nt = 0; nt < 8; nt++)
            #pragma unroll
            for (int i = 0; i < 4; i++) c[mt][nt][i] = 0.f;

    const int nslab = Kdim / 32;
    #pragma unroll
    for (int i = 0; i < 2; i++) {
        int s = tid + i*256, r = s >> 2, q8 = (s & 3) * 8;
        cpa16(sA + (uint32_t)(r*40 + q8)*2, A + (size_t)(m0 + r)*lda + q8);
        cpa16(sB + (uint32_t)(r*40 + q8)*2, B + (size_t)(n0 + r)*ldb + q8);
    }
    CP_COMMIT();

    for (int j = 0; j < nslab; j++) {
        CP_WAIT(0);
        __syncthreads();
        if (j + 1 < nslab) {
            int ec = (j + 1) * 32;
            uint32_t bo = ((j + 1) & 1) ? (uint32_t)(128*40*2) : 0u;
            #pragma unroll
            for (int i = 0; i < 2; i++) {
                int s = tid + i*256, r = s >> 2, q8 = (s & 3) * 8;
                cpa16(sA + bo + (uint32_t)(r*40 + q8)*2, A + (size_t)(m0 + r)*lda + ec + q8);
                cpa16(sB + bo + (uint32_t)(r*40 + q8)*2, B + (size_t)(n0 + r)*ldb + ec + q8);
            }
            CP_COMMIT();
        }
        const __half* Aj = As + (j & 1) * (128*40);
        const __half* Bj = Bs + (j & 1) * (128*40);
        #pragma unroll
        for (int kc = 0; kc < 2; kc++) {
            int kb = kc*16 + 2*(lane & 3);
            uint32_t af[2][4];
            #pragma unroll
            for (int mt = 0; mt < 2; mt++) {
                int r = wm*32 + mt*16 + (lane >> 2);
                af[mt][0] = *(const uint32_t*)(Aj + r*40 + kb);
                af[mt][1] = *(const uint32_t*)(Aj + (r+8)*40 + kb);
                af[mt][2] = *(const uint32_t*)(Aj + r*40 + kb + 8);
                af[mt][3] = *(const uint32_t*)(Aj + (r+8)*40 + kb + 8);
            }
            #pragma unroll
            for (int nt = 0; nt < 8; nt++) {
                int col = wn*64 + nt*8 + (lane >> 2);
                uint32_t b0 = *(const uint32_t*)(Bj + col*40 + kb);
                uint32_t b1 = *(const uint32_t*)(Bj + col*40 + kb + 8);
                mma16(c[0][nt], af[0][0], af[0][1], af[0][2], af[0][3], b0, b1);
                mma16(c[1][nt], af[1][0], af[1][1], af[1][2], af[1][3], b0, b1);
            }
        }
    }

    #pragma unroll
    for (int mt = 0; mt < 2; mt++)
        #pragma unroll
        for (int nt = 0; nt < 8; nt++)
            #pragma unroll
            for (int hf = 0; hf < 2; hf++) {
                int row = m0 + wm*32 + mt*16 + hf*8 + (lane >> 2);
                int col = n0 + wn*64 + nt*8 + (lane & 3)*2;
                float bm = biasM ? biasM[row] : 0.f;
                *(uint32_t*)(C + (size_t)z*sCz + (size_t)row*ldc + col) =
                    packh2(alpha*c[mt][nt][hf*2+0] + bm, alpha*c[mt][nt][hf*2+1] + bm);
            }
}

/* one warp per (h,c) output: 4096 warps */
__global__ __launch_bounds__(256) void rvec_kernel(const float* __restrict__ Wqk,
                                                   const float* __restrict__ bqk){
    int w = blockIdx.x * 8 + (threadIdx.x >> 5);   /* 0..4095 */
    int lane = threadIdx.x & 31;
    int h = w >> 9, cc = w & 511;
    const float* wk = Wqk + (size_t)cc * LDW + h * (2*Ee) + Ee;
    const float* bq = bqk + h * (2*Ee);
    float acc = 0.f;
    #pragma unroll
    for (int i = 0; i < 4; i++) {
        int e = lane * 4 + i * 128;
        float4 a = *(const float4*)(wk + e);
        float4 q = *(const float4*)(bq + e);
        acc += a.x*q.x + a.y*q.y + a.z*q.z + a.w*q.w;
    }
    #pragma unroll
    for (int off = 16; off; off >>= 1) acc += __shfl_xor_sync(0xffffffffu, acc, off);
    if (!lane) g_r[w] = acc * SCALE;
}

__global__ __launch_bounds__(256) void beta_kernel(const float* __restrict__ x){
    int w = blockIdx.x * 8 + (threadIdx.x >> 5);
    int lane = threadIdx.x & 31;
    int h = w >> 13, row = w & 8191;
    float acc = 0.f;
    #pragma unroll
    for (int i = 0; i < 4; i++) {
        int cc = lane * 4 + i * 128;
        float4 xv = *(const float4*)(x + (long)row * Ee + cc);
        float4 rv = *(const float4*)(g_r + h * Ee + cc);
        acc += xv.x*rv.x + xv.y*rv.y + xv.z*rv.z + xv.w*rv.w;
    }
    #pragma unroll
    for (int off = 16; off; off >>= 1) acc += __shfl_xor_sync(0xffffffffu, acc, off);
    if (!lane) g_beta[w] = acc;
}

/* fp32 SGEMM for the final out projection (error-critical) */
__global__ __launch_bounds__(256) void sgemm_kernel(
    const float* __restrict__ A, const float* __restrict__ Bm,
    const float* __restrict__ bias, float* __restrict__ C, int Ndim, int Kdim)
{
    const int m0 = blockIdx.x * 128, n0 = blockIdx.y * 128;
    const int tid = threadIdx.x, tx = tid & 15, ty = tid >> 4;
    __shared__ float As[16][132];
    __shared__ float Bs[16][128];
    float acc[8][8];
    #pragma unroll
    for (int i = 0; i < 8; i++)
        #pragma unroll
        for (int j = 0; j < 8; j++) acc[i][j] = 0.f;
    for (int kk = 0; kk < Kdim; kk += 16) {
        #pragma unroll
        for (int i = 0; i < 2; i++) {
            int slot = tid + (i << 8);
            int m = slot >> 2, k4 = (slot & 3) << 2;
            float4 av = *(const float4*)(A + (long)(m0 + m) * Kdim + kk + k4);
            As[k4+0][m] = av.x; As[k4+1][m] = av.y; As[k4+2][m] = av.z; As[k4+3][m] = av.w;
            int r = slot >> 5, c4 = (slot & 31) << 2;
            *(float4*)&Bs[r][c4] = *(const float4*)(Bm + (long)(kk + r) * Ndim + n0 + c4);
        }
        __syncthreads();
        #pragma unroll
        for (int k = 0; k < 16; k++) {
            float a[8], b[8];
            *(float4*)(a)     = *(const float4*)&As[k][ty*4];
            *(float4*)(a + 4) = *(const float4*)&As[k][ty*4 + 64];
            *(float4*)(b)     = *(const float4*)&Bs[k][tx*4];
            *(float4*)(b + 4) = *(const float4*)&Bs[k][tx*4 + 64];
            #pragma unroll
            for (int i = 0; i < 8; i++)
                #pragma unroll
                for (int j = 0; j < 8; j++) acc[i][j] += a[i] * b[j];
        }
        __syncthreads();
    }
    float b0[8];
    *(float4*)(b0)     = *(const float4*)(bias + n0 + tx*4);
    *(float4*)(b0 + 4) = *(const float4*)(bias + n0 + 64 + tx*4);
    #pragma unroll
    for (int rh = 0; rh < 2; rh++)
        #pragma unroll
        for (int i = 0; i < 4; i++) {
            int row = m0 + rh*64 + ty*4 + i;
            #pragma unroll
            for (int ch = 0; ch < 2; ch++)
                *(float4*)(C + (long)row * Ndim + n0 + ch*64 + tx*4) =
                    make_float4(acc[rh*4+i][ch*4+0] + b0[ch*4+0], acc[rh*4+i][ch*4+1] + b0[ch*4+1],
                                acc[rh*4+i][ch*4+2] + b0[ch*4+2], acc[rh*4+i][ch*4+3] + b0[ch*4+3]);
        }
}

/* =====================================================================
 * Fused attention, fp16 mma, register P, PERSISTENT q-tile in smem.
 * SMEM: bsm 0(512) lsm 512(1024) As 1536(133120, 128x520 halves)
 *       Bs 134656(3x10240) Vs 165376(17408) = 182784; Osm reuses Bs area?
 *       (epilogue Osm needs 128*66*4 = 33792 B -> reuse As region)
 * ===================================================================== */
#define AT_SMEM 182784
__global__ __launch_bounds__(256, 1) void attn_kernel(){
    extern __shared__ char sma[];
    float*  bsm = (float*)(sma);
    float*  lsm = (float*)(sma + 512);
    __half* Aq  = (__half*)(sma + 1536);           /* 128 x 520 */
    __half* Bs  = (__half*)(sma + 134656);         /* 3 x 5120  */
    __half* Vs  = (__half*)(sma + 165376);         /* 64 x 136  */
    float*  Osm = (float*)(sma + 1536);            /* epilogue reuse */
    const uint32_t sA = smem_u32(Aq), sB = smem_u32(Bs), sV = smem_u32(Vs);

    const int tid = threadIdx.x, lane = tid & 31, wid = tid >> 5;
    const int wm = wid & 3, wn = wid >> 2;
    const int qb = blockIdx.x, h = blockIdx.y, b = blockIdx.z;
    const int g = lane >> 2, tg2 = 2*(lane & 3);

    const __half* At = g_th  + ((size_t)h*BS + (size_t)b*Ss + qb*128)*Ee;
    const __half* Bx = g_xh  + ((size_t)b*Ss)*Ee;
    const __half* Vt = g_vTh + ((size_t)b*Ee + h*HDd)*Ss;

    float co[2][8][4];
    #pragma unroll
    for (int mt = 0; mt < 2; mt++)
        #pragma unroll
        for (int nt = 0; nt < 8; nt++)
            #pragma unroll
            for (int i = 0; i < 4; i++) co[mt][nt][i] = 0.f;
    float lrun[4] = {0.f, 0.f, 0.f, 0.f};

    /* one-time: full q-tile (128x512) into persistent smem */
    #pragma unroll
    for (int i = 0; i < 32; i++) {
        int s = tid + i*256;            /* 0..8191 */
        int r = s >> 6, q8 = (s & 63) * 8;
        cpa16(sA + (uint32_t)(r*520 + q8)*2, At + (size_t)r*Ee + q8);
    }
    CP_COMMIT();
    CP_WAIT(0);
    __syncthreads();

    /* B slabs 0,1 of kt=0 */
    #pragma unroll
    for (int st = 0; st < 2; st++) {
        #pragma unroll
        for (int i = 0; i < 2; i++) {
            int s = tid + i*256, r = s >> 2, q8 = (s & 3) * 8;
            cpa16(sB + (uint32_t)(st*5120 + r*40 + q8)*2, Bx + (size_t)r*Ee + st*32 + q8);
        }
        CP_COMMIT();
    }

    for (int kt = 0; kt < 16; kt++) {
        __syncthreads();                       /* PV(kt-1) done with Vs/bsm */
        if (tid < 128)
            bsm[tid] = g_beta[(size_t)h*BS + (size_t)b*Ss + kt*128 + tid];
        #pragma unroll
        for (int i = 0; i < 4; i++) {          /* V group */
            int s = tid + i*256, d = s >> 4, j8 = (s & 15) * 8;
            cpa16(sV + (uint32_t)(d*136 + j8)*2, Vt + (size_t)d*Ss + kt*128 + j8);
        }
        CP_COMMIT();

        float cs[2][8][4];
        #pragma unroll
        for (int mt = 0; mt < 2; mt++)
            #pragma unroll
            for (int nt = 0; nt < 8; nt++)
                #pragma unroll
                for (int i = 0; i < 4; i++) cs[mt][nt][i] = 0.f;

        const __half* Bk = Bx + (size_t)kt*128*Ee;

        for (int j = 0; j < 16; j++) {
            if (j < 14) {                       /* prefetch B slab j+2 */
                int ec = (j + 2) * 32;
                uint32_t bo = (uint32_t)(((j + 2) % 3) * 10240);
                #pragma unroll
                for (int i = 0; i < 2; i++) {
                    int s = tid + i*256, r = s >> 2, q8 = (s & 3) * 8;
                    cpa16(sB + bo + (uint32_t)(r*40 + q8)*2, Bk + (size_t)r*Ee + ec + q8);
                }
                CP_COMMIT();
            }
            if (j <= 1)       { CP_WAIT(3); }
            else if (j <= 13) { CP_WAIT(2); }
            else if (j == 14) { CP_WAIT(1); }
            else              { CP_WAIT(0); }
            __syncthreads();
            const __half* Bj = Bs + (j % 3) * 5120;
            #pragma unroll
            for (int kc = 0; kc < 2; kc++) {
                int kb  = kc*16 + tg2;
                int kbA = j*32 + kb;
                uint32_t af[2][4];
                #pragma unroll
                for (int mt = 0; mt < 2; mt++) {
                    int r = wm*32 + mt*16 + g;
                    af[mt][0] = *(const uint32_t*)(Aq + r*520 + kbA);
                    af[mt][1] = *(const uint32_t*)(Aq + (r+8)*520 + kbA);
                    af[mt][2] = *(const uint32_t*)(Aq + r*520 + kbA + 8);
                    af[mt][3] = *(const uint32_t*)(Aq + (r+8)*520 + kbA + 8);
                }
                #pragma unroll
                for (int nt = 0; nt < 8; nt++) {
                    int col = wn*64 + nt*8 + g;
                    uint32_t b0 = *(const uint32_t*)(Bj + col*40 + kb);
                    uint32_t b1 = *(const uint32_t*)(Bj + col*40 + kb + 8);
                    mma16(cs[0][nt], af[0][0], af[0][1], af[0][2], af[0][3], b0, b1);
                    mma16(cs[1][nt], af[1][0], af[1][1], af[1][2], af[1][3], b0, b1);
                }
            }
        }
        __syncthreads();                 /* all warps done with Bs + V visible */

        if (kt < 15) {                   /* prefetch B slabs 0,1 of kt+1 */
            const __half* Bk2 = Bx + (size_t)(kt+1)*128*Ee;
            #pragma unroll
            for (int st = 0; st < 2; st++) {
                #pragma unroll
                for (int i = 0; i < 2; i++) {
                    int s = tid + i*256, r = s >> 2, q8 = (s & 3) * 8;
                    cpa16(sB + (uint32_t)(st*5120 + r*40 + q8)*2,
                          Bk2 + (size_t)r*Ee + st*32 + q8);
                }
                CP_COMMIT();
            }
        }

        /* softmax in registers: p = exp(s/1024 + beta); pack to fp16 A-frags */
        uint32_t pA[2][8], pB[2][8];
        float part[4] = {0.f, 0.f, 0.f, 0.f};
        #pragma unroll
        for (int mt = 0; mt < 2; mt++)
            #pragma unroll
            for (int nt = 0; nt < 8; nt++) {
                int col = wn*64 + nt*8 + tg2;
                float p0 = __expf(fmaf(cs[mt][nt][0], INVMS, bsm[col]));
                float p1 = __expf(fmaf(cs[mt][nt][1], INVMS, bsm[col+1]));
                float p2 = __expf(fmaf(cs[mt][nt][2], INVMS, bsm[col]));
                float p3 = __expf(fmaf(cs[mt][nt][3], INVMS, bsm[col+1]));
                part[mt*2+0] += p0 + p1;
                part[mt*2+1] += p2 + p3;
                pA[mt][nt] = packh2(p0, p1);
                pB[mt][nt] = packh2(p2, p3);
            }
        #pragma unroll
        for (int i = 0; i < 4; i++) {
            part[i] += __shfl_xor_sync(0xffffffffu, part[i], 1);
            part[i] += __shfl_xor_sync(0xffffffffu, part[i], 2);
            lrun[i] += part[i];
        }

        if (kt < 15) { CP_WAIT(2); } else { CP_WAIT(0); }   /* V complete */
        __syncthreads();

        /* O += P @ V^T over this warp's 64-key half */
        #pragma unroll
        for (int mt = 0; mt < 2; mt++)
            #pragma unroll
            for (int kc = 0; kc < 4; kc++) {
                uint32_t a0 = pA[mt][2*kc], a1 = pB[mt][2*kc];
                uint32_t a2 = pA[mt][2*kc+1], a3 = pB[mt][2*kc+1];
                int kb = wn*64 + kc*16 + tg2;
                #pragma unroll
                for (int nt = 0; nt < 8; nt++) {
                    int d = nt*8 + g;
                    uint32_t b0 = *(const uint32_t*)(Vs + d*136 + kb);
                    uint32_t b1 = *(const uint32_t*)(Vs + d*136 + kb + 8);
                    mma16(co[mt][nt], a0, a1, a2, a3, b0, b1);
                }
            }
    }

    /* epilogue: combine the two warp-column partials via smem */
    if ((lane & 3) == 0) {
        #pragma unroll
        for (int mt = 0; mt < 2; mt++)
            #pragma unroll
            for (int hf = 0; hf < 2; hf++)
                lsm[wn*128 + wm*32 + mt*16 + hf*8 + g] = lrun[mt*2 + hf];
    }
    __syncthreads();
    if (wn == 0) {
        #pragma unroll
        for (int mt = 0; mt < 2; mt++)
            #pragma unroll
            for (int nt = 0; nt < 8; nt++)
                #pragma unroll
                for (int hf = 0; hf < 2; hf++) {
                    int row = wm*32 + mt*16 + hf*8 + g;
                    *(float2*)&Osm[row*66 + nt*8 + tg2] =
                        make_float2(co[mt][nt][hf*2+0], co[mt][nt][hf*2+1]);
                }
    }
    __syncthreads();
    if (wn == 1) {
        #pragma unroll
        for (int mt = 0; mt < 2; mt++)
            #pragma unroll
            for (int hf = 0; hf < 2; hf++) {
                int row = wm*32 + mt*16 + hf*8 + g;
                float inv = 1.0f / (lsm[row] + lsm[128 + row]);
                #pragma unroll
                for (int nt = 0; nt < 8; nt++) {
                    float2 o = *(float2*)&Osm[row*66 + nt*8 + tg2];
                    o.x = (o.x + co[mt][nt][hf*2+0]) * inv;
                    o.y = (o.y + co[mt][nt][hf*2+1]) * inv;
                    *(float2*)(g_vals + ((size_t)b*Ss + qb*128 + row)*Ee + h*HDd + nt*8 + tg2) = o;
                }
            }
    }
}

extern "C" void kernel_launch(void* const* d_in, const int* in_sizes, int n_in,
                              void* d_out, int out_size)
{
    const float* x   = (const float*)d_in[0];
    const float* Wqk = (const float*)d_in[1];
    const float* bqk = (const float*)d_in[2];
    const float* Wv  = (const float*)d_in[3];
    const float* bv  = (const float*)d_in[4];
    const float* Wo  = (const float*)d_in[5];
    const float* bo  = (const float*)d_in[6];
    float* out = (float*)d_out;

    cudaFuncSetAttribute(attn_kernel, cudaFuncAttributeMaxDynamicSharedMemorySize, AT_SMEM);
    cudaFuncSetAttribute(hgemm_p,     cudaFuncAttributeMaxDynamicSharedMemorySize, HG_SMEM);

    void *pWq, *pWk, *pMt, *pXh, *pTh, *pWvT, *pVT, *pVals;
    cudaGetSymbolAddress(&pWq,  g_Wqh);
    cudaGetSymbolAddress(&pWk,  g_Wkh);
    cudaGetSymbolAddress(&pMt,  g_Mth);
    cudaGetSymbolAddress(&pXh,  g_xh);
    cudaGetSymbolAddress(&pTh,  g_th);
    cudaGetSymbolAddress(&pWvT, g_WvTh);
    cudaGetSymbolAddress(&pVT,  g_vTh);
    cudaGetSymbolAddress(&pVals, g_vals);

    xcvt_kernel<<<BS*Ee/2048, 256>>>(x);
    qkcvt_kernel<<<1024, 256>>>(Wqk);
    wtrans_kernel<<<dim3(16, 16), dim3(32, 8)>>>(Wv);
    rvec_kernel<<<512, 256>>>(Wqk, bqk);
    beta_kernel<<<8192, 256>>>(x);

    /* Mt[h] = 1024*SCALE * Wk . Wq^T */
    hgemm_p<<<dim3(4, 4, 8), 256, HG_SMEM>>>(
        (const __half*)pWk, Ee, (long)Ee*Ee,
        (const __half*)pWq, Ee, (long)Ee*Ee,
        nullptr, (__half*)pMt, Ee, (long)Ee*Ee, Ee, SCALE * 1024.0f);

    /* t*1024 = x @ Mt^T */
    hgemm_p<<<dim3(64, 4, 8), 256, HG_SMEM>>>(
        (const __half*)pXh, Ee, 0,
        (const __half*)pMt, Ee, (long)Ee*Ee,
        nullptr, (__half*)pTh, Ee, (long)BS*Ee, Ee, 1.0f);

    /* v^T[b][d][s] = Wv^T . x^T + bv */
    hgemm_p<<<dim3(4, 16, 4), 256, HG_SMEM>>>(
        (const __half*)pWvT, Ee, 0,
        (const __half*)pXh, Ee, (long)Ss*Ee,
        bv, (__half*)pVT, Ss, (long)Ee*Ss, Ee, 1.0f);

    attn_kernel<<<dim3(16, Hh, Bb), 256, AT_SMEM>>>();

    /* out = vals @ Wo + bo  (fp32, error-critical) */
    sgemm_kernel<<<dim3(64, 4), 256>>>((const float*)pVals, Wo, bo, out, Ee, Ee);
}